// round 1
// baseline (speedup 1.0000x reference)
#include <cuda_runtime.h>
#include <cstdint>
#include <cstddef>

#define BB 2
#define NNODE 2048
#define DDIM 256
#define HH 8
#define HDIM 32
#define EEDGE 65536
#define KTOP 1024
#define NWRD (NNODE/32)   // 64 u32 words per adjacency row

// ---------------- scratch (device globals: no allocation allowed) ----------------
__device__ float    g_topo[BB*NNODE];
__device__ float    g_colmask[BB*NNODE];
__device__ unsigned g_edge[NNODE*NWRD];
__device__ float    g_Q[(size_t)BB*HH*NNODE*HDIM];
__device__ float    g_K[(size_t)BB*HH*NNODE*HDIM];
__device__ float    g_V[(size_t)BB*HH*NNODE*HDIM];
__device__ float    g_attn[(size_t)BB*NNODE*DDIM];

// ---------------- zero edge bits + column mask ----------------
__global__ void k_zero() {
    int i = blockIdx.x * blockDim.x + threadIdx.x;
    if (i < NNODE*NWRD) g_edge[i] = 0u;
    if (i < BB*NNODE)   g_colmask[i] = 0.0f;
}

// ---------------- scatter edges into bitmask ----------------
__global__ void k_scatter(const int* __restrict__ ei) {
    int e = blockIdx.x * blockDim.x + threadIdx.x;
    if (e >= EEDGE) return;
    int r = ei[e];
    int c = ei[EEDGE + e];
    atomicOr(&g_edge[r * NWRD + (c >> 5)], 1u << (c & 31));
}

// ---------------- topo scores: relu(x@g1^T + b1)@g2^T + b2 ----------------
// 8 nodes per block, 128 threads (one hidden unit per thread)
__global__ void k_topo(const float* __restrict__ x,
                       const float* __restrict__ g1w, const float* __restrict__ g1b,
                       const float* __restrict__ g2w, const float* __restrict__ g2b) {
    __shared__ float xs[8][DDIM];
    __shared__ float rs[8][4];
    int t = threadIdx.x;
    int base = blockIdx.x * 8;   // flattened node index in [0, B*N)

    const float4* xv = (const float4*)(x + (size_t)base * DDIM);
    float4* xsv = (float4*)&xs[0][0];
    #pragma unroll
    for (int r = 0; r < 4; r++) xsv[t + r * 128] = xv[t + r * 128];
    __syncthreads();

    float acc[8];
    #pragma unroll
    for (int nn = 0; nn < 8; nn++) acc[nn] = 0.0f;

    const float* wrow = g1w + t * DDIM;
    for (int k = 0; k < DDIM; k++) {
        float w = wrow[k];
        #pragma unroll
        for (int nn = 0; nn < 8; nn++) acc[nn] += xs[nn][k] * w;
    }
    float b1 = g1b[t];
    float w2 = g2w[t];
    #pragma unroll
    for (int nn = 0; nn < 8; nn++) {
        float h = fmaxf(acc[nn] + b1, 0.0f);
        acc[nn] = h * w2;
    }
    int lane = t & 31, wrp = t >> 5;
    #pragma unroll
    for (int nn = 0; nn < 8; nn++) {
        float v = acc[nn];
        #pragma unroll
        for (int o = 16; o > 0; o >>= 1) v += __shfl_down_sync(0xffffffffu, v, o);
        if (lane == 0) rs[nn][wrp] = v;
    }
    __syncthreads();
    if (t < 8) {
        float v = rs[t][0] + rs[t][1] + rs[t][2] + rs[t][3];
        g_topo[base + t] = v + g2b[0];
    }
}

// ---------------- exact top-k via bitonic sort (value desc, index asc) ----------------
__global__ void k_topk() {
    __shared__ unsigned long long keys[NNODE];
    int b = blockIdx.x;
    int t = threadIdx.x;  // 1024 threads
    for (int i = t; i < NNODE; i += 1024) {
        float v = g_topo[b * NNODE + i];
        unsigned u = __float_as_uint(v);
        u = (u & 0x80000000u) ? ~u : (u | 0x80000000u);  // ascending orderable
        unsigned kv = ~u;                                 // descending by value
        keys[i] = ((unsigned long long)kv << 32) | (unsigned)i;
    }
    __syncthreads();
    for (unsigned k = 2; k <= NNODE; k <<= 1) {
        for (unsigned j = k >> 1; j > 0; j >>= 1) {
            for (int i = t; i < NNODE; i += 1024) {
                unsigned ixj = (unsigned)i ^ j;
                if (ixj > (unsigned)i) {
                    bool up = ((i & k) == 0);
                    unsigned long long a = keys[i], bb = keys[ixj];
                    if ((a > bb) == up) { keys[i] = bb; keys[ixj] = a; }
                }
            }
            __syncthreads();
        }
    }
    if (t < KTOP) {
        unsigned idx = (unsigned)(keys[t] & 0xffffffffu);
        g_colmask[b * NNODE + idx] = 1.0f;
    }
}

// ---------------- generic tiled fp32 GEMM: Out = A[M,256] @ W^T[256,256] + bias ----------------
// HEADM: write to [b, h, n, hd] layout (for Q/K/V); else plain [m, c]
template<bool HEADM>
__global__ void k_gemm(const float* __restrict__ A, const float* __restrict__ W,
                       const float* __restrict__ bias, float* __restrict__ Out) {
    __shared__ float As[16][65];
    __shared__ float Ws[16][65];
    int tid = threadIdx.x;        // 256
    int tx = tid & 15, ty = tid >> 4;
    int m0 = blockIdx.x * 64, c0 = blockIdx.y * 64;

    float acc[4][4];
    #pragma unroll
    for (int i = 0; i < 4; i++)
        #pragma unroll
        for (int j = 0; j < 4; j++) acc[i][j] = 0.0f;

    for (int k0 = 0; k0 < DDIM; k0 += 16) {
        #pragma unroll
        for (int r = 0; r < 4; r++) {
            int m = (tid >> 4) + r * 16;
            int kk = tid & 15;
            As[kk][m] = A[(size_t)(m0 + m) * DDIM + k0 + kk];
            Ws[kk][m] = W[(size_t)(c0 + m) * DDIM + k0 + kk];
        }
        __syncthreads();
        #pragma unroll
        for (int kk = 0; kk < 16; kk++) {
            float a[4], w[4];
            #pragma unroll
            for (int i = 0; i < 4; i++) a[i] = As[kk][ty + i * 16];
            #pragma unroll
            for (int j = 0; j < 4; j++) w[j] = Ws[kk][tx + j * 16];
            #pragma unroll
            for (int i = 0; i < 4; i++)
                #pragma unroll
                for (int j = 0; j < 4; j++) acc[i][j] += a[i] * w[j];
        }
        __syncthreads();
    }
    #pragma unroll
    for (int i = 0; i < 4; i++) {
        int m = m0 + ty + i * 16;
        int b = m / NNODE, n = m % NNODE;
        #pragma unroll
        for (int j = 0; j < 4; j++) {
            int c = c0 + tx + j * 16;
            float v = acc[i][j] + bias[c];
            if (HEADM) {
                Out[(((size_t)b * HH + (c >> 5)) * NNODE + n) * HDIM + (c & 31)] = v;
            } else {
                Out[(size_t)m * DDIM + c] = v;
            }
        }
    }
}

// ---------------- write sparse_mask output: [B,H,N,N] broadcast over H ----------------
__global__ void k_maskwrite(float* __restrict__ outMask) {
    __shared__ float row[NNODE];
    int i = blockIdx.x;   // query row
    int b = blockIdx.y;
    int t = threadIdx.x;  // 256
    const float* cm = g_colmask + b * NNODE;
    const unsigned* er = g_edge + i * NWRD;
    for (int j = t; j < NNODE; j += 256) {
        unsigned bit = (er[j >> 5] >> (j & 31)) & 1u;
        row[j] = (bit != 0u || cm[j] != 0.0f) ? 1.0f : 0.0f;
    }
    __syncthreads();
    const float4* rv = (const float4*)row;
    size_t base = ((size_t)b * HH) * NNODE * NNODE + (size_t)i * NNODE;
    for (int h = 0; h < HH; h++) {
        float4* ov = (float4*)(outMask + base + (size_t)h * NNODE * NNODE);
        for (int j = t; j < NNODE / 4; j += 256) ov[j] = rv[j];
    }
}

// ---------------- fused masked attention (flash-style, one query row per thread) ----------------
__global__ void __launch_bounds__(128) k_attn() {
    __shared__ float Ks[64][HDIM];
    __shared__ float Vs[64][HDIM];
    __shared__ float cms[64];
    int t = threadIdx.x;
    int bh = blockIdx.y;
    int b = bh / HH;
    int i = blockIdx.x * 128 + t;

    const float scale = 0.17677669529663687f;  // 1/sqrt(32)
    float q[HDIM];
    const float* Qr = g_Q + ((size_t)bh * NNODE + i) * HDIM;
    #pragma unroll
    for (int d = 0; d < HDIM; d++) q[d] = Qr[d] * scale;

    float Z = 0.0f, S = 0.0f;
    float acc[HDIM];
    #pragma unroll
    for (int d = 0; d < HDIM; d++) acc[d] = 0.0f;

    const unsigned* er = g_edge + i * NWRD;
    const float* cm = g_colmask + b * NNODE;
    const float* Kb = g_K + (size_t)bh * NNODE * HDIM;
    const float* Vb = g_V + (size_t)bh * NNODE * HDIM;

    for (int jb = 0; jb < NNODE; jb += 64) {
        __syncthreads();
        const float4* kv4 = (const float4*)(Kb + (size_t)jb * HDIM);
        const float4* vv4 = (const float4*)(Vb + (size_t)jb * HDIM);
        float4* ks4 = (float4*)&Ks[0][0];
        float4* vs4 = (float4*)&Vs[0][0];
        #pragma unroll
        for (int r = 0; r < 4; r++) {
            ks4[t + r * 128] = kv4[t + r * 128];
            vs4[t + r * 128] = vv4[t + r * 128];
        }
        if (t < 64) cms[t] = cm[jb + t];
        __syncthreads();

        unsigned e0 = er[jb >> 5];
        unsigned e1 = er[(jb >> 5) + 1];
        #pragma unroll 2
        for (int jj = 0; jj < 64; jj++) {
            float s = 0.0f;
            #pragma unroll
            for (int d = 0; d < HDIM; d++) s += q[d] * Ks[jj][d];
            // scores are O(1) with these weight scales; skip max-subtraction
            // (ratio exp(s)*mask / (Σ exp(s)*mask + 1e-8*Σ exp(s)) is shift-invariant)
            float p = __expf(s);
            Z += p;
            unsigned bit = (jj < 32) ? (e0 >> jj) : (e1 >> (jj - 32));
            float pm = ((bit & 1u) != 0u || cms[jj] != 0.0f) ? p : 0.0f;
            S += pm;
            #pragma unroll
            for (int d = 0; d < HDIM; d++) acc[d] += pm * Vs[jj][d];
        }
    }
    float inv = 1.0f / (S + 1e-8f * Z);
    int h = bh % HH;
    float* o = g_attn + ((size_t)(b * NNODE + i)) * DDIM + h * HDIM;
    #pragma unroll
    for (int d = 0; d < HDIM; d++) o[d] = acc[d] * inv;
}

// ---------------- launch ----------------
extern "C" void kernel_launch(void* const* d_in, const int* in_sizes, int n_in,
                              void* d_out, int out_size) {
    (void)in_sizes; (void)n_in; (void)out_size;
    const float* x   = (const float*)d_in[0];
    const int*   ei  = (const int*)  d_in[1];
    const float* qw  = (const float*)d_in[2];
    const float* qb  = (const float*)d_in[3];
    const float* kw  = (const float*)d_in[4];
    const float* kb  = (const float*)d_in[5];
    const float* vw  = (const float*)d_in[6];
    const float* vb  = (const float*)d_in[7];
    const float* ow  = (const float*)d_in[8];
    const float* ob  = (const float*)d_in[9];
    const float* g1w = (const float*)d_in[10];
    const float* g1b = (const float*)d_in[11];
    const float* g2w = (const float*)d_in[12];
    const float* g2b = (const float*)d_in[13];

    float* out = (float*)d_out;
    float* outMask = out + (size_t)BB * NNODE * DDIM;

    float *pQ, *pK, *pV, *pAttn;
    cudaGetSymbolAddress((void**)&pQ, g_Q);
    cudaGetSymbolAddress((void**)&pK, g_K);
    cudaGetSymbolAddress((void**)&pV, g_V);
    cudaGetSymbolAddress((void**)&pAttn, g_attn);

    k_zero<<<512, 256>>>();
    k_scatter<<<EEDGE / 256, 256>>>(ei);
    k_topo<<<BB * NNODE / 8, 128>>>(x, g1w, g1b, g2w, g2b);
    k_topk<<<BB, 1024>>>();

    dim3 ggrid(64, 4);
    k_gemm<true><<<ggrid, 256>>>(x, qw, qb, pQ);
    k_gemm<true><<<ggrid, 256>>>(x, kw, kb, pK);
    k_gemm<true><<<ggrid, 256>>>(x, vw, vb, pV);

    k_maskwrite<<<dim3(NNODE, BB), 256>>>(outMask);

    k_attn<<<dim3(NNODE / 128, BB * HH), 128>>>();

    k_gemm<false><<<ggrid, 256>>>(pAttn, ow, ob, out);
}

// round 2
// speedup vs baseline: 1.1037x; 1.1037x over previous
#include <cuda_runtime.h>
#include <cstdint>
#include <cstddef>

#define BB 2
#define NNODE 2048
#define DDIM 256
#define HH 8
#define HDIM 32
#define EEDGE 65536
#define KTOP 1024
#define NWRD (NNODE/32)   // 64 u32 words per adjacency row

typedef unsigned long long u64;

// ---------------- packed f32x2 helpers (Blackwell FFMA2: 2x fp32 throughput) ----------------
__device__ __forceinline__ u64 ffma2(u64 a, u64 b, u64 c) {
    u64 d; asm("fma.rn.f32x2 %0, %1, %2, %3;" : "=l"(d) : "l"(a), "l"(b), "l"(c)); return d;
}
__device__ __forceinline__ u64 fadd2(u64 a, u64 b) {
    u64 d; asm("add.rn.f32x2 %0, %1, %2;" : "=l"(d) : "l"(a), "l"(b)); return d;
}
__device__ __forceinline__ u64 fmul2(u64 a, u64 b) {
    u64 d; asm("mul.rn.f32x2 %0, %1, %2;" : "=l"(d) : "l"(a), "l"(b)); return d;
}
__device__ __forceinline__ u64 pk2(float lo, float hi) {
    u64 d; asm("mov.b64 %0, {%1, %2};" : "=l"(d) : "f"(lo), "f"(hi)); return d;
}
__device__ __forceinline__ void upk2(u64 v, float& lo, float& hi) {
    asm("mov.b64 {%0, %1}, %2;" : "=f"(lo), "=f"(hi) : "l"(v));
}

// ---------------- scratch (device globals: no allocation allowed) ----------------
__device__ float    g_topo[BB*NNODE];
__device__ float    g_colmask[BB*NNODE];
__device__ unsigned g_edge[NNODE*NWRD];
__device__ float    g_Q[(size_t)BB*HH*NNODE*HDIM];
__device__ float    g_K[(size_t)BB*HH*NNODE*HDIM];
__device__ float    g_V[(size_t)BB*HH*NNODE*HDIM];
__device__ float    g_attn[(size_t)BB*NNODE*DDIM];

// ---------------- zero edge bits ----------------
__global__ void k_zero() {
    int i = blockIdx.x * blockDim.x + threadIdx.x;
    if (i < NNODE*NWRD) g_edge[i] = 0u;
}

// ---------------- scatter edges into bitmask ----------------
__global__ void k_scatter(const int* __restrict__ ei) {
    int e = blockIdx.x * blockDim.x + threadIdx.x;
    if (e >= EEDGE) return;
    int r = ei[e];
    int c = ei[EEDGE + e];
    atomicOr(&g_edge[r * NWRD + (c >> 5)], 1u << (c & 31));
}

// ---------------- topo scores: relu(x@g1^T + b1)@g2^T + b2 (f32x2 packed) ----------------
// 8 nodes per block, 128 threads (one hidden unit per thread)
__global__ void __launch_bounds__(128) k_topo(const float* __restrict__ x,
                       const float* __restrict__ g1w, const float* __restrict__ g1b,
                       const float* __restrict__ g2w, const float* __restrict__ g2b) {
    __shared__ __align__(16) float xs[8][DDIM];
    __shared__ float rs[8][4];
    int t = threadIdx.x;
    int base = blockIdx.x * 8;   // flattened node index in [0, B*N)

    const float4* xv = (const float4*)(x + (size_t)base * DDIM);
    float4* xsv = (float4*)&xs[0][0];
    #pragma unroll
    for (int r = 0; r < 4; r++) xsv[t + r * 128] = xv[t + r * 128];
    __syncthreads();

    u64 acc[8];
    #pragma unroll
    for (int nn = 0; nn < 8; nn++) acc[nn] = 0ull;

    const ulonglong2* wrow = (const ulonglong2*)(g1w + (size_t)t * DDIM);
    #pragma unroll 4
    for (int k4 = 0; k4 < DDIM/4; k4++) {
        ulonglong2 wv = wrow[k4];
        #pragma unroll
        for (int nn = 0; nn < 8; nn++) {
            ulonglong2 xp = ((const ulonglong2*)xs[nn])[k4];
            acc[nn] = ffma2(wv.x, xp.x, acc[nn]);
            acc[nn] = ffma2(wv.y, xp.y, acc[nn]);
        }
    }
    float b1 = g1b[t];
    float w2s = g2w[t];
    float res[8];
    #pragma unroll
    for (int nn = 0; nn < 8; nn++) {
        float lo, hi; upk2(acc[nn], lo, hi);
        float h = fmaxf(lo + hi + b1, 0.0f);
        res[nn] = h * w2s;
    }
    int lane = t & 31, wrp = t >> 5;
    #pragma unroll
    for (int nn = 0; nn < 8; nn++) {
        float v = res[nn];
        #pragma unroll
        for (int o = 16; o > 0; o >>= 1) v += __shfl_down_sync(0xffffffffu, v, o);
        if (lane == 0) rs[nn][wrp] = v;
    }
    __syncthreads();
    if (t < 8) {
        float v = rs[t][0] + rs[t][1] + rs[t][2] + rs[t][3];
        g_topo[base + t] = v + g2b[0];
    }
}

// ---------------- exact top-k via 4-pass byte radix select ----------------
// semantics: top KTOP values, ties broken by lowest index (== jax.lax.top_k)
__global__ void __launch_bounds__(256) k_topk() {
    __shared__ unsigned keys[NNODE];
    __shared__ unsigned hist[256];
    __shared__ unsigned scanbuf[256];
    __shared__ unsigned sh_prefix, sh_remain;
    int b = blockIdx.x;
    int t = threadIdx.x;  // 256 threads, 8 elements each

    for (int i = t; i < NNODE; i += 256) {
        unsigned u = __float_as_uint(g_topo[b * NNODE + i]);
        u = (u & 0x80000000u) ? ~u : (u | 0x80000000u);  // monotone ascending uint
        keys[i] = u;
    }
    unsigned prefix = 0, remain = KTOP;
    __syncthreads();

    for (int shift = 24; shift >= 0; shift -= 8) {
        hist[t] = 0;
        __syncthreads();
        for (int i = t; i < NNODE; i += 256) {
            unsigned k = keys[i];
            bool in_group = (shift == 24) || ((k >> (shift + 8)) == prefix);
            if (in_group) atomicAdd(&hist[(k >> shift) & 255], 1u);
        }
        __syncthreads();
        if (t == 0) {
            unsigned cum = 0; int v = 255;
            for (; v > 0; v--) {
                unsigned c = hist[v];
                if (cum + c >= remain) break;
                cum += c;
            }
            sh_prefix = (prefix << 8) | (unsigned)v;
            sh_remain = remain - cum;
        }
        __syncthreads();
        prefix = sh_prefix;
        remain = sh_remain;
        __syncthreads();
    }
    unsigned T = prefix;  // value of the KTOP-th largest key; take `remain` of the ==T set

    // exclusive scan of eq-counts in index order (8 consecutive elems per thread)
    unsigned cnt = 0;
    #pragma unroll
    for (int u = 0; u < 8; u++) {
        if (keys[t * 8 + u] == T) cnt++;
    }
    scanbuf[t] = cnt;
    __syncthreads();
    for (int ofs = 1; ofs < 256; ofs <<= 1) {
        unsigned v = scanbuf[t];
        unsigned add = (t >= ofs) ? scanbuf[t - ofs] : 0u;
        __syncthreads();
        scanbuf[t] = v + add;
        __syncthreads();
    }
    unsigned taken = scanbuf[t] - cnt;  // eq elements before my chunk
    #pragma unroll
    for (int u = 0; u < 8; u++) {
        int i = t * 8 + u;
        unsigned k = keys[i];
        float m = 0.0f;
        if (k > T) m = 1.0f;
        else if (k == T) {
            if (taken < remain) m = 1.0f;
            taken++;
        }
        g_colmask[b * NNODE + i] = m;
    }
}

// ---------------- tiled fp32 GEMM with f32x2: Out = A[M,256] @ W^T[256,256] + bias ----------------
// tile 128(M) x 64(C), 256 threads, 8 rows x 4 cols per thread
// HEADM: write to [b, h, n, hd] layout (for Q/K/V); else plain [m, c]
template<bool HEADM>
__global__ void __launch_bounds__(256) k_gemm(const float* __restrict__ A, const float* __restrict__ W,
                       const float* __restrict__ bias, float* __restrict__ Out) {
    __shared__ __align__(16) u64   As2[16][130];  // A values duplicated into both f32x2 lanes
    __shared__ __align__(16) float Ws[16][68];
    int tid = threadIdx.x;
    int tx = tid & 15;       // col group: cols c0 + tx*4 + {0..3}
    int rg = tid >> 4;       // row group: rows m0 + rg*8 + {0..7}
    int m0 = blockIdx.x * 128, c0 = blockIdx.y * 64;
    int lkk = tid & 15, lm = tid >> 4;

    u64 acc[8][2];
    #pragma unroll
    for (int i = 0; i < 8; i++) { acc[i][0] = 0ull; acc[i][1] = 0ull; }

    for (int k0 = 0; k0 < DDIM; k0 += 16) {
        #pragma unroll
        for (int rr = 0; rr < 8; rr++) {
            int m = lm + 16 * rr;
            float v = A[(size_t)(m0 + m) * DDIM + k0 + lkk];
            As2[lkk][m] = pk2(v, v);
        }
        #pragma unroll
        for (int rr = 0; rr < 4; rr++) {
            int c = lm + 16 * rr;
            Ws[lkk][c] = W[(size_t)(c0 + c) * DDIM + k0 + lkk];
        }
        __syncthreads();
        #pragma unroll
        for (int kk = 0; kk < 16; kk++) {
            float4 w4 = *(const float4*)&Ws[kk][tx * 4];
            u64 w01 = pk2(w4.x, w4.y), w23 = pk2(w4.z, w4.w);
            const u64* arow = &As2[kk][rg * 8];
            #pragma unroll
            for (int ii = 0; ii < 8; ii += 2) {
                ulonglong2 a2 = *(const ulonglong2*)&arow[ii];
                acc[ii][0]     = ffma2(a2.x, w01, acc[ii][0]);
                acc[ii][1]     = ffma2(a2.x, w23, acc[ii][1]);
                acc[ii + 1][0] = ffma2(a2.y, w01, acc[ii + 1][0]);
                acc[ii + 1][1] = ffma2(a2.y, w23, acc[ii + 1][1]);
            }
        }
        __syncthreads();
    }

    float4 b4 = *(const float4*)&bias[c0 + tx * 4];
    #pragma unroll
    for (int ii = 0; ii < 8; ii++) {
        int m = m0 + rg * 8 + ii;
        int bb = m / NNODE, n = m % NNODE;
        float f0, f1, f2, f3;
        upk2(acc[ii][0], f0, f1);
        upk2(acc[ii][1], f2, f3);
        float4 o4 = make_float4(f0 + b4.x, f1 + b4.y, f2 + b4.z, f3 + b4.w);
        int c = c0 + tx * 4;
        if (HEADM) {
            int h = c >> 5, cw = c & 31;
            *(float4*)&Out[(((size_t)(bb * HH + h)) * NNODE + n) * HDIM + cw] = o4;
        } else {
            *(float4*)&Out[(size_t)m * DDIM + c] = o4;
        }
    }
}

// ---------------- write sparse_mask output: [B,H,N,N] broadcast over H ----------------
__global__ void k_maskwrite(float* __restrict__ outMask) {
    __shared__ float row[NNODE];
    int i = blockIdx.x;   // query row
    int b = blockIdx.y;
    int t = threadIdx.x;  // 256
    const float* cm = g_colmask + b * NNODE;
    const unsigned* er = g_edge + i * NWRD;
    for (int j = t; j < NNODE; j += 256) {
        unsigned bit = (er[j >> 5] >> (j & 31)) & 1u;
        row[j] = (bit != 0u || cm[j] != 0.0f) ? 1.0f : 0.0f;
    }
    __syncthreads();
    const float4* rv = (const float4*)row;
    size_t base = ((size_t)b * HH) * NNODE * NNODE + (size_t)i * NNODE;
    for (int h = 0; h < HH; h++) {
        float4* ov = (float4*)(outMask + base + (size_t)h * NNODE * NNODE);
        for (int j = t; j < NNODE / 4; j += 256) ov[j] = rv[j];
    }
}

// ---------------- fused masked attention (flash-style, f32x2 packed) ----------------
__global__ void __launch_bounds__(128) k_attn() {
    __shared__ __align__(16) float Ks[64][HDIM];
    __shared__ __align__(16) float Vs[64][HDIM];
    __shared__ float cms[64];
    int t = threadIdx.x;
    int bh = blockIdx.y;
    int b = bh >> 3;
    int i = blockIdx.x * 128 + t;

    const float scale = 0.17677669529663687f;  // 1/sqrt(32)
    u64 q2[16];
    {
        const u64* Qr = (const u64*)(g_Q + ((size_t)bh * NNODE + i) * HDIM);
        u64 sc2 = pk2(scale, scale);
        #pragma unroll
        for (int d2 = 0; d2 < 16; d2++) q2[d2] = fmul2(Qr[d2], sc2);
    }

    float Z = 0.0f, S = 0.0f;
    u64 acc2[16];
    #pragma unroll
    for (int d2 = 0; d2 < 16; d2++) acc2[d2] = 0ull;

    const unsigned* er = g_edge + i * NWRD;
    const float* cm = g_colmask + b * NNODE;
    const float* Kb = g_K + (size_t)bh * NNODE * HDIM;
    const float* Vb = g_V + (size_t)bh * NNODE * HDIM;

    for (int jb = 0; jb < NNODE; jb += 64) {
        __syncthreads();
        const float4* kv4 = (const float4*)(Kb + (size_t)jb * HDIM);
        const float4* vv4 = (const float4*)(Vb + (size_t)jb * HDIM);
        float4* ks4 = (float4*)&Ks[0][0];
        float4* vs4 = (float4*)&Vs[0][0];
        #pragma unroll
        for (int r = 0; r < 4; r++) {
            ks4[t + r * 128] = kv4[t + r * 128];
            vs4[t + r * 128] = vv4[t + r * 128];
        }
        if (t < 64) cms[t] = cm[jb + t];
        __syncthreads();

        u64 ew = (u64)er[jb >> 5] | ((u64)er[(jb >> 5) + 1] << 32);
        #pragma unroll 4
        for (int jj = 0; jj < 64; jj++) {
            // packed dot product: s = q . K[jj]
            const ulonglong2* k2p = (const ulonglong2*)Ks[jj];
            u64 c0 = 0ull, c1 = 0ull, c2 = 0ull, c3 = 0ull;
            #pragma unroll
            for (int u = 0; u < 4; u++) {
                ulonglong2 kx = k2p[2 * u];
                ulonglong2 ky = k2p[2 * u + 1];
                c0 = ffma2(q2[4 * u + 0], kx.x, c0);
                c1 = ffma2(q2[4 * u + 1], kx.y, c1);
                c2 = ffma2(q2[4 * u + 2], ky.x, c2);
                c3 = ffma2(q2[4 * u + 3], ky.y, c3);
            }
            c0 = fadd2(c0, c1); c2 = fadd2(c2, c3); c0 = fadd2(c0, c2);
            float slo, shi; upk2(c0, slo, shi);
            float s = slo + shi;
            // shift-invariant ratio: skip max-subtraction (scores O(1))
            float p = __expf(s);
            Z += p;
            bool on = (((ew >> jj) & 1ull) != 0ull) || (cms[jj] != 0.0f);
            float pm = on ? p : 0.0f;
            S += pm;
            u64 pm2 = pk2(pm, pm);
            const ulonglong2* v2p = (const ulonglong2*)Vs[jj];
            #pragma unroll
            for (int u = 0; u < 8; u++) {
                ulonglong2 vx = v2p[u];
                acc2[2 * u]     = ffma2(pm2, vx.x, acc2[2 * u]);
                acc2[2 * u + 1] = ffma2(pm2, vx.y, acc2[2 * u + 1]);
            }
        }
    }
    float inv = 1.0f / (S + 1e-8f * Z);
    u64 inv2 = pk2(inv, inv);
    int h = bh & 7;
    u64* o = (u64*)(g_attn + ((size_t)(b * NNODE + i)) * DDIM + h * HDIM);
    #pragma unroll
    for (int d2 = 0; d2 < 16; d2++) o[d2] = fmul2(acc2[d2], inv2);
}

// ---------------- launch ----------------
extern "C" void kernel_launch(void* const* d_in, const int* in_sizes, int n_in,
                              void* d_out, int out_size) {
    (void)in_sizes; (void)n_in; (void)out_size;
    const float* x   = (const float*)d_in[0];
    const int*   ei  = (const int*)  d_in[1];
    const float* qw  = (const float*)d_in[2];
    const float* qb  = (const float*)d_in[3];
    const float* kw  = (const float*)d_in[4];
    const float* kb  = (const float*)d_in[5];
    const float* vw  = (const float*)d_in[6];
    const float* vb  = (const float*)d_in[7];
    const float* ow  = (const float*)d_in[8];
    const float* ob  = (const float*)d_in[9];
    const float* g1w = (const float*)d_in[10];
    const float* g1b = (const float*)d_in[11];
    const float* g2w = (const float*)d_in[12];
    const float* g2b = (const float*)d_in[13];

    float* out = (float*)d_out;
    float* outMask = out + (size_t)BB * NNODE * DDIM;

    float *pQ, *pK, *pV, *pAttn;
    cudaGetSymbolAddress((void**)&pQ, g_Q);
    cudaGetSymbolAddress((void**)&pK, g_K);
    cudaGetSymbolAddress((void**)&pV, g_V);
    cudaGetSymbolAddress((void**)&pAttn, g_attn);

    k_zero<<<512, 256>>>();
    k_scatter<<<EEDGE / 256, 256>>>(ei);
    k_topo<<<BB * NNODE / 8, 128>>>(x, g1w, g1b, g2w, g2b);
    k_topk<<<BB, 256>>>();

    dim3 ggrid(BB * NNODE / 128, DDIM / 64);
    k_gemm<true><<<ggrid, 256>>>(x, qw, qb, pQ);
    k_gemm<true><<<ggrid, 256>>>(x, kw, kb, pK);
    k_gemm<true><<<ggrid, 256>>>(x, vw, vb, pV);

    k_maskwrite<<<dim3(NNODE, BB), 256>>>(outMask);

    k_attn<<<dim3(NNODE / 128, BB * HH), 128>>>();

    k_gemm<false><<<ggrid, 256>>>(pAttn, ow, ob, out);
}

// round 3
// speedup vs baseline: 1.9178x; 1.7377x over previous
#include <cuda_runtime.h>
#include <cuda_bf16.h>
#include <cstdint>
#include <cstddef>

#define BB 2
#define NNODE 2048
#define DDIM 256
#define HH 8
#define HDIM 32
#define EEDGE 65536
#define KTOP 1024
#define NWRD (NNODE/32)   // 64 u32 words per adjacency row

typedef unsigned u32;
typedef unsigned long long u64;

// ---------------- packed f32x2 helpers ----------------
__device__ __forceinline__ u64 ffma2(u64 a, u64 b, u64 c) {
    u64 d; asm("fma.rn.f32x2 %0, %1, %2, %3;" : "=l"(d) : "l"(a), "l"(b), "l"(c)); return d;
}
__device__ __forceinline__ u64 pk2(float lo, float hi) {
    u64 d; asm("mov.b64 %0, {%1, %2};" : "=l"(d) : "f"(lo), "f"(hi)); return d;
}
__device__ __forceinline__ void upk2(u64 v, float& lo, float& hi) {
    asm("mov.b64 {%0, %1}, %2;" : "=f"(lo), "=f"(hi) : "l"(v));
}
// pack two fp32 -> bf16x2 (hi goes to upper 16 bits)
__device__ __forceinline__ u32 cvt2(float hi, float lo) {
    u32 r; asm("cvt.rn.bf16x2.f32 %0, %1, %2;" : "=r"(r) : "f"(hi), "f"(lo)); return r;
}
__device__ __forceinline__ float bf16rt(float x) {
    return __bfloat162float(__float2bfloat16_rn(x));
}
// mma.sync m16n8k16 bf16 row.col, fp32 accumulate
__device__ __forceinline__ void mma16816(float c[4], const u32 a[4], u32 b0, u32 b1) {
    asm volatile(
        "mma.sync.aligned.m16n8k16.row.col.f32.bf16.bf16.f32 "
        "{%0,%1,%2,%3},{%4,%5,%6,%7},{%8,%9},{%0,%1,%2,%3};"
        : "+f"(c[0]), "+f"(c[1]), "+f"(c[2]), "+f"(c[3])
        : "r"(a[0]), "r"(a[1]), "r"(a[2]), "r"(a[3]), "r"(b0), "r"(b1));
}

// ---------------- scratch (device globals) ----------------
__device__ float g_topo[BB*NNODE];
__device__ u32   g_edge[NNODE*NWRD];
__device__ u32   g_colbits[BB*NWRD];
// bf16 hi/lo operand arrays. Q/K layout [bh][n][32]; V layout [bh][d][n] (transposed)
__device__ __nv_bfloat16 g_Qh[(size_t)BB*HH*NNODE*HDIM];
__device__ __nv_bfloat16 g_Ql[(size_t)BB*HH*NNODE*HDIM];
__device__ __nv_bfloat16 g_Kh[(size_t)BB*HH*NNODE*HDIM];
__device__ __nv_bfloat16 g_Kl[(size_t)BB*HH*NNODE*HDIM];
__device__ __nv_bfloat16 g_Vh[(size_t)BB*HH*NNODE*HDIM];
__device__ __nv_bfloat16 g_Vl[(size_t)BB*HH*NNODE*HDIM];
__device__ float g_attn[(size_t)BB*NNODE*DDIM];

// ---------------- zero edge bits + colbits ----------------
__global__ void k_zero() {
    int i = blockIdx.x * blockDim.x + threadIdx.x;
    if (i < NNODE*NWRD) g_edge[i] = 0u;
    if (i < BB*NWRD)    g_colbits[i] = 0u;
}

// ---------------- scatter edges into bitmask ----------------
__global__ void k_scatter(const int* __restrict__ ei) {
    int e = blockIdx.x * blockDim.x + threadIdx.x;
    if (e >= EEDGE) return;
    int r = ei[e];
    int c = ei[EEDGE + e];
    atomicOr(&g_edge[r * NWRD + (c >> 5)], 1u << (c & 31));
}

// ---------------- topo scores (f32x2 packed) ----------------
__global__ void __launch_bounds__(128) k_topo(const float* __restrict__ x,
                       const float* __restrict__ g1w, const float* __restrict__ g1b,
                       const float* __restrict__ g2w, const float* __restrict__ g2b) {
    __shared__ __align__(16) float xs[8][DDIM];
    __shared__ float rs[8][4];
    int t = threadIdx.x;
    int base = blockIdx.x * 8;

    const float4* xv = (const float4*)(x + (size_t)base * DDIM);
    float4* xsv = (float4*)&xs[0][0];
    #pragma unroll
    for (int r = 0; r < 4; r++) xsv[t + r * 128] = xv[t + r * 128];
    __syncthreads();

    u64 acc[8];
    #pragma unroll
    for (int nn = 0; nn < 8; nn++) acc[nn] = 0ull;

    const ulonglong2* wrow = (const ulonglong2*)(g1w + (size_t)t * DDIM);
    #pragma unroll 4
    for (int k4 = 0; k4 < DDIM/4; k4++) {
        ulonglong2 wv = wrow[k4];
        #pragma unroll
        for (int nn = 0; nn < 8; nn++) {
            ulonglong2 xp = ((const ulonglong2*)xs[nn])[k4];
            acc[nn] = ffma2(wv.x, xp.x, acc[nn]);
            acc[nn] = ffma2(wv.y, xp.y, acc[nn]);
        }
    }
    float b1 = g1b[t];
    float w2s = g2w[t];
    float res[8];
    #pragma unroll
    for (int nn = 0; nn < 8; nn++) {
        float lo, hi; upk2(acc[nn], lo, hi);
        float h = fmaxf(lo + hi + b1, 0.0f);
        res[nn] = h * w2s;
    }
    int lane = t & 31, wrp = t >> 5;
    #pragma unroll
    for (int nn = 0; nn < 8; nn++) {
        float v = res[nn];
        #pragma unroll
        for (int o = 16; o > 0; o >>= 1) v += __shfl_down_sync(0xffffffffu, v, o);
        if (lane == 0) rs[nn][wrp] = v;
    }
    __syncthreads();
    if (t < 8) {
        float v = rs[t][0] + rs[t][1] + rs[t][2] + rs[t][3];
        g_topo[base + t] = v + g2b[0];
    }
}

// ---------------- exact top-k: radix select with PARALLEL threshold find ----------------
__global__ void __launch_bounds__(256) k_topk() {
    __shared__ u32 keys[NNODE];
    __shared__ u32 hist[256];
    __shared__ u32 sb[256];
    __shared__ u32 scn[256];
    __shared__ u32 sh_prefix, sh_remain;
    int b = blockIdx.x;
    int t = threadIdx.x;  // 256 threads

    for (int i = t; i < NNODE; i += 256) {
        u32 u = __float_as_uint(g_topo[b * NNODE + i]);
        u = (u & 0x80000000u) ? ~u : (u | 0x80000000u);  // monotone ascending
        keys[i] = u;
    }
    u32 prefix = 0, remain = KTOP;
    __syncthreads();

    for (int shift = 24; shift >= 0; shift -= 8) {
        hist[t] = 0;
        __syncthreads();
        for (int i = t; i < NNODE; i += 256) {
            u32 k = keys[i];
            bool in_group = (shift == 24) || ((k >> (shift + 8)) == prefix);
            if (in_group) atomicAdd(&hist[(k >> shift) & 255], 1u);
        }
        __syncthreads();
        // parallel inclusive SUFFIX sum: sb[v] = sum_{u>=v} hist[u]
        sb[t] = hist[t];
        __syncthreads();
        for (int ofs = 1; ofs < 256; ofs <<= 1) {
            u32 add = (t + ofs < 256) ? sb[t + ofs] : 0u;
            __syncthreads();
            sb[t] += add;
            __syncthreads();
        }
        u32 above = (t == 255) ? 0u : sb[t + 1];
        if (sb[t] >= remain && above < remain) {
            sh_prefix = (prefix << 8) | (u32)t;
            sh_remain = remain - above;
        }
        __syncthreads();
        prefix = sh_prefix;
        remain = sh_remain;
        __syncthreads();
    }
    u32 T = prefix;  // KTOP-th largest key; take `remain` of the ==T set in index order

    u32 cnt = 0;
    #pragma unroll
    for (int u = 0; u < 8; u++) if (keys[t * 8 + u] == T) cnt++;
    scn[t] = cnt;
    __syncthreads();
    for (int ofs = 1; ofs < 256; ofs <<= 1) {
        u32 v = scn[t];
        u32 add = (t >= ofs) ? scn[t - ofs] : 0u;
        __syncthreads();
        scn[t] = v + add;
        __syncthreads();
    }
    u32 taken = scn[t] - cnt;
    u32 byte = 0;
    #pragma unroll
    for (int u = 0; u < 8; u++) {
        u32 k = keys[t * 8 + u];
        bool m = false;
        if (k > T) m = true;
        else if (k == T) { if (taken < remain) m = true; taken++; }
        if (m) byte |= (1u << u);
    }
    atomicOr(&g_colbits[b * NWRD + (t >> 2)], byte << ((t & 3) * 8));
}

// ---------------- tiled fp32 GEMM (f32x2 core) with 3 epilogues ----------------
// MODE 0: fp32 out [m][256]
// MODE 1: bf16 hi/lo out, [bh][n][32], value = (acc+bias)*scale   (Q with scale, K scale=1)
// MODE 2: bf16 hi/lo out TRANSPOSED, [bh][d][n]                   (V)
template<int MODE>
__global__ void __launch_bounds__(256) k_gemm(const float* __restrict__ A, const float* __restrict__ W,
                       const float* __restrict__ bias, float* __restrict__ OutF,
                       u32* __restrict__ OutH, u32* __restrict__ OutL, float scale) {
    __shared__ __align__(16) u64   As2[16][130];
    __shared__ __align__(16) float Ws[16][68];
    int tid = threadIdx.x;
    int tx = tid & 15;       // col group: cols c0 + tx*4 + {0..3}
    int rg = tid >> 4;       // row group: rows m0 + rg*8 + {0..7}
    int m0 = blockIdx.x * 128, c0 = blockIdx.y * 64;
    int lkk = tid & 15, lm = tid >> 4;

    u64 acc[8][2];
    #pragma unroll
    for (int i = 0; i < 8; i++) { acc[i][0] = 0ull; acc[i][1] = 0ull; }

    for (int k0 = 0; k0 < DDIM; k0 += 16) {
        #pragma unroll
        for (int rr = 0; rr < 8; rr++) {
            int m = lm + 16 * rr;
            float v = A[(size_t)(m0 + m) * DDIM + k0 + lkk];
            As2[lkk][m] = pk2(v, v);
        }
        #pragma unroll
        for (int rr = 0; rr < 4; rr++) {
            int c = lm + 16 * rr;
            Ws[lkk][c] = W[(size_t)(c0 + c) * DDIM + k0 + lkk];
        }
        __syncthreads();
        #pragma unroll
        for (int kk = 0; kk < 16; kk++) {
            float4 w4 = *(const float4*)&Ws[kk][tx * 4];
            u64 w01 = pk2(w4.x, w4.y), w23 = pk2(w4.z, w4.w);
            const u64* arow = &As2[kk][rg * 8];
            #pragma unroll
            for (int ii = 0; ii < 8; ii += 2) {
                ulonglong2 a2 = *(const ulonglong2*)&arow[ii];
                acc[ii][0]     = ffma2(a2.x, w01, acc[ii][0]);
                acc[ii][1]     = ffma2(a2.x, w23, acc[ii][1]);
                acc[ii + 1][0] = ffma2(a2.y, w01, acc[ii + 1][0]);
                acc[ii + 1][1] = ffma2(a2.y, w23, acc[ii + 1][1]);
            }
        }
        __syncthreads();
    }

    float4 b4 = *(const float4*)&bias[c0 + tx * 4];
    int c = c0 + tx * 4;                 // 4 consecutive cols (same head)
    int h = (c >> 5) & 7, cw = c & 31;
    int bb = m0 >> 11;                   // m0 multiple of 128, no batch straddle
    int n0 = (m0 & 2047) + rg * 8;

    if (MODE == 2) {
        // gather columns over the 8 consecutive rows -> transposed bf16 stores
        float vals[8][4];
        #pragma unroll
        for (int ii = 0; ii < 8; ii++) {
            float f0, f1, f2, f3;
            upk2(acc[ii][0], f0, f1);
            upk2(acc[ii][1], f2, f3);
            vals[ii][0] = f0 + b4.x; vals[ii][1] = f1 + b4.y;
            vals[ii][2] = f2 + b4.z; vals[ii][3] = f3 + b4.w;
        }
        #pragma unroll
        for (int jj = 0; jj < 4; jj++) {
            int d = cw + jj;
            u32 wh[4], wl[4];
            #pragma unroll
            for (int p = 0; p < 4; p++) {
                float v0 = vals[2*p][jj],   v1 = vals[2*p+1][jj];
                float h0 = bf16rt(v0), h1 = bf16rt(v1);
                wh[p] = cvt2(h1, h0);
                wl[p] = cvt2(v1 - h1, v0 - h0);
            }
            size_t widx = (((size_t)(bb * HH + h) * HDIM + d) * NNODE + n0) >> 1;
            *(uint4*)&OutH[widx] = make_uint4(wh[0], wh[1], wh[2], wh[3]);
            *(uint4*)&OutL[widx] = make_uint4(wl[0], wl[1], wl[2], wl[3]);
        }
    } else {
        #pragma unroll
        for (int ii = 0; ii < 8; ii++) {
            int m = m0 + rg * 8 + ii;
            float f0, f1, f2, f3;
            upk2(acc[ii][0], f0, f1);
            upk2(acc[ii][1], f2, f3);
            f0 += b4.x; f1 += b4.y; f2 += b4.z; f3 += b4.w;
            if (MODE == 0) {
                *(float4*)&OutF[(size_t)m * DDIM + c] = make_float4(f0, f1, f2, f3);
            } else {
                f0 *= scale; f1 *= scale; f2 *= scale; f3 *= scale;
                float h0 = bf16rt(f0), h1 = bf16rt(f1), h2 = bf16rt(f2), h3 = bf16rt(f3);
                int n = n0 + ii;
                size_t widx = ((size_t)(bb * HH + h) * NNODE + n) * (HDIM/2) + (cw >> 1);
                *(uint2*)&OutH[widx] = make_uint2(cvt2(h1, h0), cvt2(h3, h2));
                *(uint2*)&OutL[widx] = make_uint2(cvt2(f1 - h1, f0 - h0), cvt2(f3 - h3, f2 - h2));
            }
        }
    }
}

// ---------------- write sparse_mask output from bits: [B,H,N,N] ----------------
__global__ void k_maskwrite(float* __restrict__ outMask) {
    __shared__ float row[NNODE];
    int i = blockIdx.x;
    int b = blockIdx.y;
    int t = threadIdx.x;  // 256
    for (int j = t; j < NNODE; j += 256) {
        u32 w = g_edge[i * NWRD + (j >> 5)] | g_colbits[b * NWRD + (j >> 5)];
        row[j] = ((w >> (j & 31)) & 1u) ? 1.0f : 0.0f;
    }
    __syncthreads();
    const float4* rv = (const float4*)row;
    size_t base = ((size_t)b * HH) * NNODE * NNODE + (size_t)i * NNODE;
    for (int h = 0; h < HH; h++) {
        float4* ov = (float4*)(outMask + base + (size_t)h * NNODE * NNODE);
        for (int j = t; j < NNODE / 4; j += 256) ov[j] = rv[j];
    }
}

// ---------------- fused masked attention on tensor pipe (bf16 hi/lo mma) ----------------
// block: 256 thr (8 warps), one (bh), 128 query rows. warp w owns rows 16w..16w+15.
__global__ void __launch_bounds__(256) k_attn() {
    __shared__ u32 Ksh[128][20], Ksl[128][20];   // K bf16-pair words, padded
    __shared__ u32 Vth[32][68],  Vtl[32][68];    // V^T bf16-pair words, padded
    __shared__ u32 eW[128][4];                   // merged edge|col bits per row per 128-j tile

    int tid = threadIdx.x;
    int wp = tid >> 5, lane = tid & 31;
    int gid = lane >> 2, tig = lane & 3;
    int bh = blockIdx.y, b = bh >> 3, h = bh & 7;
    int i0 = blockIdx.x * 128;
    int rlo = wp * 16 + gid;          // local row in [0,128)

    const u32* gqh = (const u32*)g_Qh;
    const u32* gql = (const u32*)g_Ql;
    const u32* gkh = (const u32*)g_Kh;
    const u32* gkl = (const u32*)g_Kl;
    const u32* gvh = (const u32*)g_Vh;
    const u32* gvl = (const u32*)g_Vl;

    // Q A-fragments (scale already folded in)
    u32 qh[2][4], ql[2][4];
    {
        size_t blo = ((size_t)bh * NNODE + i0 + rlo) * 16;
        size_t bhi = blo + 8 * 16;
        #pragma unroll
        for (int kc = 0; kc < 2; kc++) {
            qh[kc][0] = gqh[blo + kc*8 + tig];
            qh[kc][1] = gqh[bhi + kc*8 + tig];
            qh[kc][2] = gqh[blo + kc*8 + tig + 4];
            qh[kc][3] = gqh[bhi + kc*8 + tig + 4];
            ql[kc][0] = gql[blo + kc*8 + tig];
            ql[kc][1] = gql[bhi + kc*8 + tig];
            ql[kc][2] = gql[blo + kc*8 + tig + 4];
            ql[kc][3] = gql[bhi + kc*8 + tig + 4];
        }
    }

    float oc[4][4];
    #pragma unroll
    for (int vt = 0; vt < 4; vt++)
        #pragma unroll
        for (int e = 0; e < 4; e++) oc[vt][e] = 0.0f;
    float zlo = 0.0f, zhi = 0.0f, slo = 0.0f, shi = 0.0f;

    for (int j0 = 0; j0 < NNODE; j0 += 128) {
        __syncthreads();
        // stage K hi/lo
        for (int idx = tid; idx < 2048; idx += 256) {
            int r = idx >> 4, w = idx & 15;
            size_t gw = ((size_t)bh * NNODE + j0 + r) * 16 + w;
            Ksh[r][w] = gkh[gw];
            Ksl[r][w] = gkl[gw];
        }
        // stage V^T hi/lo
        for (int idx = tid; idx < 2048; idx += 256) {
            int d = idx >> 6, a = idx & 63;
            size_t gw = ((size_t)bh * HDIM + d) * (NNODE/2) + (j0 >> 1) + a;
            Vth[d][a] = gvh[gw];
            Vtl[d][a] = gvl[gw];
        }
        // stage merged mask bits
        {
            int wb = j0 >> 5;
            for (int idx = tid; idx < 512; idx += 256) {
                int r = idx >> 2, w = idx & 3;
                eW[r][w] = g_edge[(size_t)(i0 + r) * NWRD + wb + w] | g_colbits[b * NWRD + wb + w];
            }
        }
        __syncthreads();

        #pragma unroll 1
        for (int sub = 0; sub < 4; sub++) {
            // ---- S = Q K^T (3-term bf16) ----
            float sc[4][4];
            #pragma unroll
            for (int nt = 0; nt < 4; nt++)
                #pragma unroll
                for (int e = 0; e < 4; e++) sc[nt][e] = 0.0f;
            #pragma unroll
            for (int kc = 0; kc < 2; kc++)
                #pragma unroll
                for (int nt = 0; nt < 4; nt++) {
                    int jr = sub * 32 + nt * 8 + gid;
                    u32 b0h = Ksh[jr][kc*8 + tig], b1h = Ksh[jr][kc*8 + tig + 4];
                    u32 b0l = Ksl[jr][kc*8 + tig], b1l = Ksl[jr][kc*8 + tig + 4];
                    mma16816(sc[nt], qh[kc], b0h, b1h);
                    mma16816(sc[nt], ql[kc], b0h, b1h);
                    mma16816(sc[nt], qh[kc], b0l, b1l);
                }
            // ---- exp + mask + row sums ----
            u32 wlo = eW[wp * 16 + gid][sub];
            u32 whi = eW[wp * 16 + gid + 8][sub];
            float pm[4][4];
            #pragma unroll
            for (int nt = 0; nt < 4; nt++) {
                float p0 = __expf(sc[nt][0]);
                float p1 = __expf(sc[nt][1]);
                float p2 = __expf(sc[nt][2]);
                float p3 = __expf(sc[nt][3]);
                int bp = nt * 8 + tig * 2;
                float m0 = ((wlo >> bp) & 1u) ? p0 : 0.0f;
                float m1 = ((wlo >> (bp + 1)) & 1u) ? p1 : 0.0f;
                float m2 = ((whi >> bp) & 1u) ? p2 : 0.0f;
                float m3 = ((whi >> (bp + 1)) & 1u) ? p3 : 0.0f;
                zlo += p0 + p1; zhi += p2 + p3;
                slo += m0 + m1; shi += m2 + m3;
                pm[nt][0] = m0; pm[nt][1] = m1; pm[nt][2] = m2; pm[nt][3] = m3;
            }
            // ---- P -> bf16 hi/lo A-fragments (C layout == A layout) ----
            u32 ph[2][4], pl[2][4];
            #pragma unroll
            for (int kc = 0; kc < 2; kc++) {
                int na = kc * 2, nb = kc * 2 + 1;
                float h00 = bf16rt(pm[na][0]), h01 = bf16rt(pm[na][1]);
                float h02 = bf16rt(pm[na][2]), h03 = bf16rt(pm[na][3]);
                float h10 = bf16rt(pm[nb][0]), h11 = bf16rt(pm[nb][1]);
                float h12 = bf16rt(pm[nb][2]), h13 = bf16rt(pm[nb][3]);
                ph[kc][0] = cvt2(h01, h00);
                ph[kc][1] = cvt2(h03, h02);
                ph[kc][2] = cvt2(h11, h10);
                ph[kc][3] = cvt2(h13, h12);
                pl[kc][0] = cvt2(pm[na][1] - h01, pm[na][0] - h00);
                pl[kc][1] = cvt2(pm[na][3] - h03, pm[na][2] - h02);
                pl[kc][2] = cvt2(pm[nb][1] - h11, pm[nb][0] - h10);
                pl[kc][3] = cvt2(pm[nb][3] - h13, pm[nb][2] - h12);
            }
            // ---- O += P V (3-term bf16) ----
            #pragma unroll
            for (int kc = 0; kc < 2; kc++)
                #pragma unroll
                for (int vt = 0; vt < 4; vt++) {
                    int d = vt * 8 + gid;
                    int wj = sub * 16 + kc * 8 + tig;
                    u32 b0h = Vth[d][wj], b1h = Vth[d][wj + 4];
                    u32 b0l = Vtl[d][wj], b1l = Vtl[d][wj + 4];
                    mma16816(oc[vt], ph[kc], b0h, b1h);
                    mma16816(oc[vt], pl[kc], b0h, b1h);
                    mma16816(oc[vt], ph[kc], b0l, b1l);
                }
        }
    }

    // reduce Z/S across the quad (lanes with same row)
    #pragma unroll
    for (int o = 1; o <= 2; o <<= 1) {
        zlo += __shfl_xor_sync(0xffffffffu, zlo, o);
        zhi += __shfl_xor_sync(0xffffffffu, zhi, o);
        slo += __shfl_xor_sync(0xffffffffu, slo, o);
        shi += __shfl_xor_sync(0xffffffffu, shi, o);
    }
    float invlo = 1.0f / (slo + 1e-8f * zlo);
    float invhi = 1.0f / (shi + 1e-8f * zhi);

    int nlo = i0 + wp * 16 + gid;
    int nhi = nlo + 8;
    size_t olo = ((size_t)(b * NNODE + nlo)) * DDIM + h * HDIM;
    size_t ohi = ((size_t)(b * NNODE + nhi)) * DDIM + h * HDIM;
    #pragma unroll
    for (int vt = 0; vt < 4; vt++) {
        int d = vt * 8 + tig * 2;
        *(float2*)&g_attn[olo + d] = make_float2(oc[vt][0] * invlo, oc[vt][1] * invlo);
        *(float2*)&g_attn[ohi + d] = make_float2(oc[vt][2] * invhi, oc[vt][3] * invhi);
    }
}

// ---------------- launch ----------------
extern "C" void kernel_launch(void* const* d_in, const int* in_sizes, int n_in,
                              void* d_out, int out_size) {
    (void)in_sizes; (void)n_in; (void)out_size;
    const float* x   = (const float*)d_in[0];
    const int*   ei  = (const int*)  d_in[1];
    const float* qw  = (const float*)d_in[2];
    const float* qb  = (const float*)d_in[3];
    const float* kw  = (const float*)d_in[4];
    const float* kb  = (const float*)d_in[5];
    const float* vw  = (const float*)d_in[6];
    const float* vb  = (const float*)d_in[7];
    const float* ow  = (const float*)d_in[8];
    const float* ob  = (const float*)d_in[9];
    const float* g1w = (const float*)d_in[10];
    const float* g1b = (const float*)d_in[11];
    const float* g2w = (const float*)d_in[12];
    const float* g2b = (const float*)d_in[13];

    float* out = (float*)d_out;
    float* outMask = out + (size_t)BB * NNODE * DDIM;

    u32 *pQh, *pQl, *pKh, *pKl, *pVh, *pVl;
    float* pAttn;
    cudaGetSymbolAddress((void**)&pQh, g_Qh);
    cudaGetSymbolAddress((void**)&pQl, g_Ql);
    cudaGetSymbolAddress((void**)&pKh, g_Kh);
    cudaGetSymbolAddress((void**)&pKl, g_Kl);
    cudaGetSymbolAddress((void**)&pVh, g_Vh);
    cudaGetSymbolAddress((void**)&pVl, g_Vl);
    cudaGetSymbolAddress((void**)&pAttn, g_attn);

    const float qscale = 0.17677669529663687f;  // 1/sqrt(32)

    k_zero<<<512, 256>>>();
    k_scatter<<<EEDGE / 256, 256>>>(ei);
    k_topo<<<BB * NNODE / 8, 128>>>(x, g1w, g1b, g2w, g2b);
    k_topk<<<BB, 256>>>();

    dim3 ggrid(BB * NNODE / 128, DDIM / 64);
    k_gemm<1><<<ggrid, 256>>>(x, qw, qb, nullptr, pQh, pQl, qscale);
    k_gemm<1><<<ggrid, 256>>>(x, kw, kb, nullptr, pKh, pKl, 1.0f);
    k_gemm<2><<<ggrid, 256>>>(x, vw, vb, nullptr, pVh, pVl, 1.0f);

    k_maskwrite<<<dim3(NNODE, BB), 256>>>(outMask);

    k_attn<<<dim3(NNODE / 128, BB * HH), 256>>>();

    k_gemm<0><<<ggrid, 256>>>(pAttn, ow, ob, out, nullptr, nullptr, 1.0f);
}

// round 5
// speedup vs baseline: 1.9398x; 1.0115x over previous
#include <cuda_runtime.h>
#include <cuda_bf16.h>
#include <cstdint>
#include <cstddef>

#define BB 2
#define NNODE 2048
#define DDIM 256
#define HH 8
#define HDIM 32
#define EEDGE 65536
#define KTOP 1024
#define NWRD (NNODE/32)   // 64 u32 words per adjacency row

typedef unsigned u32;
typedef unsigned long long u64;

// ---------------- packed f32x2 helpers ----------------
__device__ __forceinline__ u64 ffma2(u64 a, u64 b, u64 c) {
    u64 d; asm("fma.rn.f32x2 %0, %1, %2, %3;" : "=l"(d) : "l"(a), "l"(b), "l"(c)); return d;
}
__device__ __forceinline__ u64 pk2(float lo, float hi) {
    u64 d; asm("mov.b64 %0, {%1, %2};" : "=l"(d) : "f"(lo), "f"(hi)); return d;
}
__device__ __forceinline__ void upk2(u64 v, float& lo, float& hi) {
    asm("mov.b64 {%0, %1}, %2;" : "=f"(lo), "=f"(hi) : "l"(v));
}
// pack two fp32 -> bf16x2 (hi goes to upper 16 bits)
__device__ __forceinline__ u32 cvt2(float hi, float lo) {
    u32 r; asm("cvt.rn.bf16x2.f32 %0, %1, %2;" : "=r"(r) : "f"(hi), "f"(lo)); return r;
}
__device__ __forceinline__ float bf16rt(float x) {
    return __bfloat162float(__float2bfloat16_rn(x));
}
// mma.sync m16n8k16 bf16 row.col, fp32 accumulate
__device__ __forceinline__ void mma16816(float c[4], const u32 a[4], u32 b0, u32 b1) {
    asm volatile(
        "mma.sync.aligned.m16n8k16.row.col.f32.bf16.bf16.f32 "
        "{%0,%1,%2,%3},{%4,%5,%6,%7},{%8,%9},{%0,%1,%2,%3};"
        : "+f"(c[0]), "+f"(c[1]), "+f"(c[2]), "+f"(c[3])
        : "r"(a[0]), "r"(a[1]), "r"(a[2]), "r"(a[3]), "r"(b0), "r"(b1));
}

// ---------------- scratch (device globals) ----------------
__device__ float g_topo[BB*NNODE];
__device__ u32   g_edge[NNODE*NWRD];
__device__ u32   g_colbits[BB*NWRD];
// bf16 hi/lo operand arrays. Q/K layout [bh][n][32]; V layout [bh][d][n] (transposed)
__device__ __nv_bfloat16 g_Qh[(size_t)BB*HH*NNODE*HDIM];
__device__ __nv_bfloat16 g_Ql[(size_t)BB*HH*NNODE*HDIM];
__device__ __nv_bfloat16 g_Kh[(size_t)BB*HH*NNODE*HDIM];
__device__ __nv_bfloat16 g_Kl[(size_t)BB*HH*NNODE*HDIM];
__device__ __nv_bfloat16 g_Vh[(size_t)BB*HH*NNODE*HDIM];
__device__ __nv_bfloat16 g_Vl[(size_t)BB*HH*NNODE*HDIM];
__device__ float g_attn[(size_t)BB*NNODE*DDIM];

// ---------------- zero edge bits + colbits ----------------
__global__ void k_zero() {
    int i = blockIdx.x * blockDim.x + threadIdx.x;
    if (i < NNODE*NWRD) g_edge[i] = 0u;
    if (i < BB*NWRD)    g_colbits[i] = 0u;
}

// ---------------- scatter edges into bitmask ----------------
__global__ void k_scatter(const int* __restrict__ ei) {
    int e = blockIdx.x * blockDim.x + threadIdx.x;
    if (e >= EEDGE) return;
    int r = ei[e];
    int c = ei[EEDGE + e];
    atomicOr(&g_edge[r * NWRD + (c >> 5)], 1u << (c & 31));
}

// ---------------- topo scores (f32x2 packed) ----------------
__global__ void __launch_bounds__(128) k_topo(const float* __restrict__ x,
                       const float* __restrict__ g1w, const float* __restrict__ g1b,
                       const float* __restrict__ g2w, const float* __restrict__ g2b) {
    __shared__ __align__(16) float xs[8][DDIM];
    __shared__ float rs[8][4];
    int t = threadIdx.x;
    int base = blockIdx.x * 8;

    const float4* xv = (const float4*)(x + (size_t)base * DDIM);
    float4* xsv = (float4*)&xs[0][0];
    #pragma unroll
    for (int r = 0; r < 4; r++) xsv[t + r * 128] = xv[t + r * 128];
    __syncthreads();

    u64 acc[8];
    #pragma unroll
    for (int nn = 0; nn < 8; nn++) acc[nn] = 0ull;

    const ulonglong2* wrow = (const ulonglong2*)(g1w + (size_t)t * DDIM);
    #pragma unroll 4
    for (int k4 = 0; k4 < DDIM/4; k4++) {
        ulonglong2 wv = wrow[k4];
        #pragma unroll
        for (int nn = 0; nn < 8; nn++) {
            ulonglong2 xp = ((const ulonglong2*)xs[nn])[k4];
            acc[nn] = ffma2(wv.x, xp.x, acc[nn]);
            acc[nn] = ffma2(wv.y, xp.y, acc[nn]);
        }
    }
    float b1 = g1b[t];
    float w2s = g2w[t];
    float res[8];
    #pragma unroll
    for (int nn = 0; nn < 8; nn++) {
        float lo, hi; upk2(acc[nn], lo, hi);
        float h = fmaxf(lo + hi + b1, 0.0f);
        res[nn] = h * w2s;
    }
    int lane = t & 31, wrp = t >> 5;
    #pragma unroll
    for (int nn = 0; nn < 8; nn++) {
        float v = res[nn];
        #pragma unroll
        for (int o = 16; o > 0; o >>= 1) v += __shfl_down_sync(0xffffffffu, v, o);
        if (lane == 0) rs[nn][wrp] = v;
    }
    __syncthreads();
    if (t < 8) {
        float v = rs[t][0] + rs[t][1] + rs[t][2] + rs[t][3];
        g_topo[base + t] = v + g2b[0];
    }
}

// ---------------- exact top-k: radix select with parallel threshold find ----------------
__global__ void __launch_bounds__(256) k_topk() {
    __shared__ u32 keys[NNODE];
    __shared__ u32 hist[256];
    __shared__ u32 sb[256];
    __shared__ u32 scn[256];
    __shared__ u32 sh_prefix, sh_remain;
    int b = blockIdx.x;
    int t = threadIdx.x;  // 256 threads

    for (int i = t; i < NNODE; i += 256) {
        u32 u = __float_as_uint(g_topo[b * NNODE + i]);
        u = (u & 0x80000000u) ? ~u : (u | 0x80000000u);  // monotone ascending
        keys[i] = u;
    }
    u32 prefix = 0, remain = KTOP;
    __syncthreads();

    for (int shift = 24; shift >= 0; shift -= 8) {
        hist[t] = 0;
        __syncthreads();
        for (int i = t; i < NNODE; i += 256) {
            u32 k = keys[i];
            bool in_group = (shift == 24) || ((k >> (shift + 8)) == prefix);
            if (in_group) atomicAdd(&hist[(k >> shift) & 255], 1u);
        }
        __syncthreads();
        // parallel inclusive SUFFIX sum: sb[v] = sum_{u>=v} hist[u]
        sb[t] = hist[t];
        __syncthreads();
        for (int ofs = 1; ofs < 256; ofs <<= 1) {
            u32 add = (t + ofs < 256) ? sb[t + ofs] : 0u;
            __syncthreads();
            sb[t] += add;
            __syncthreads();
        }
        u32 above = (t == 255) ? 0u : sb[t + 1];
        if (sb[t] >= remain && above < remain) {
            sh_prefix = (prefix << 8) | (u32)t;
            sh_remain = remain - above;
        }
        __syncthreads();
        prefix = sh_prefix;
        remain = sh_remain;
        __syncthreads();
    }
    u32 T = prefix;  // KTOP-th largest key; take `remain` of the ==T set in index order

    u32 cnt = 0;
    #pragma unroll
    for (int u = 0; u < 8; u++) if (keys[t * 8 + u] == T) cnt++;
    scn[t] = cnt;
    __syncthreads();
    for (int ofs = 1; ofs < 256; ofs <<= 1) {
        u32 v = scn[t];
        u32 add = (t >= ofs) ? scn[t - ofs] : 0u;
        __syncthreads();
        scn[t] = v + add;
        __syncthreads();
    }
    u32 taken = scn[t] - cnt;
    u32 byte = 0;
    #pragma unroll
    for (int u = 0; u < 8; u++) {
        u32 k = keys[t * 8 + u];
        bool m = false;
        if (k > T) m = true;
        else if (k == T) { if (taken < remain) m = true; taken++; }
        if (m) byte |= (1u << u);
    }
    atomicOr(&g_colbits[b * NWRD + (t >> 2)], byte << ((t & 3) * 8));
}

// ---------------- fused QKV GEMM (f32x2 core), blockIdx.z selects Q/K/V ----------------
// z=0: Q -> bf16 hi/lo [bh][n][32], scaled by 1/sqrt(hd)
// z=1: K -> bf16 hi/lo [bh][n][32]
// z=2: V -> bf16 hi/lo TRANSPOSED [bh][d][n]
__global__ void __launch_bounds__(256) k_gemmQKV(
        const float* __restrict__ A,
        const float* __restrict__ qw, const float* __restrict__ qb,
        const float* __restrict__ kw, const float* __restrict__ kb,
        const float* __restrict__ vw, const float* __restrict__ vb,
        u32* __restrict__ Qh, u32* __restrict__ Ql,
        u32* __restrict__ Kh, u32* __restrict__ Kl,
        u32* __restrict__ Vh, u32* __restrict__ Vl, float qscale) {
    __shared__ __align__(16) u64   As2[16][130];
    __shared__ __align__(16) float Ws[16][68];
    int mode = blockIdx.z;
    const float* W    = (mode == 0) ? qw : (mode == 1) ? kw : vw;
    const float* bias = (mode == 0) ? qb : (mode == 1) ? kb : vb;
    u32* OutH = (mode == 0) ? Qh : (mode == 1) ? Kh : Vh;
    u32* OutL = (mode == 0) ? Ql : (mode == 1) ? Kl : Vl;
    float scale = (mode == 0) ? qscale : 1.0f;

    int tid = threadIdx.x;
    int tx = tid & 15;       // col group: cols c0 + tx*4 + {0..3}
    int rg = tid >> 4;       // row group: rows m0 + rg*8 + {0..7}
    int m0 = blockIdx.x * 128, c0 = blockIdx.y * 64;
    int lkk = tid & 15, lm = tid >> 4;

    u64 acc[8][2];
    #pragma unroll
    for (int i = 0; i < 8; i++) { acc[i][0] = 0ull; acc[i][1] = 0ull; }

    for (int k0 = 0; k0 < DDIM; k0 += 16) {
        #pragma unroll
        for (int rr = 0; rr < 8; rr++) {
            int m = lm + 16 * rr;
            float v = A[(size_t)(m0 + m) * DDIM + k0 + lkk];
            As2[lkk][m] = pk2(v, v);
        }
        #pragma unroll
        for (int rr = 0; rr < 4; rr++) {
            int c = lm + 16 * rr;
            Ws[lkk][c] = W[(size_t)(c0 + c) * DDIM + k0 + lkk];
        }
        __syncthreads();
        #pragma unroll
        for (int kk = 0; kk < 16; kk++) {
            float4 w4 = *(const float4*)&Ws[kk][tx * 4];
            u64 w01 = pk2(w4.x, w4.y), w23 = pk2(w4.z, w4.w);
            const u64* arow = &As2[kk][rg * 8];
            #pragma unroll
            for (int ii = 0; ii < 8; ii += 2) {
                ulonglong2 a2 = *(const ulonglong2*)&arow[ii];
                acc[ii][0]     = ffma2(a2.x, w01, acc[ii][0]);
                acc[ii][1]     = ffma2(a2.x, w23, acc[ii][1]);
                acc[ii + 1][0] = ffma2(a2.y, w01, acc[ii + 1][0]);
                acc[ii + 1][1] = ffma2(a2.y, w23, acc[ii + 1][1]);
            }
        }
        __syncthreads();
    }

    float4 b4 = *(const float4*)&bias[c0 + tx * 4];
    int c = c0 + tx * 4;                 // 4 consecutive cols (same head)
    int h = (c >> 5) & 7, cw = c & 31;
    int bb = m0 >> 11;                   // m0 multiple of 128, no batch straddle
    int n0 = (m0 & 2047) + rg * 8;

    if (mode == 2) {
        float vals[8][4];
        #pragma unroll
        for (int ii = 0; ii < 8; ii++) {
            float f0, f1, f2, f3;
            upk2(acc[ii][0], f0, f1);
            upk2(acc[ii][1], f2, f3);
            vals[ii][0] = f0 + b4.x; vals[ii][1] = f1 + b4.y;
            vals[ii][2] = f2 + b4.z; vals[ii][3] = f3 + b4.w;
        }
        #pragma unroll
        for (int jj = 0; jj < 4; jj++) {
            int d = cw + jj;
            u32 wh[4], wl[4];
            #pragma unroll
            for (int p = 0; p < 4; p++) {
                float v0 = vals[2*p][jj],   v1 = vals[2*p+1][jj];
                float h0 = bf16rt(v0), h1 = bf16rt(v1);
                wh[p] = cvt2(h1, h0);
                wl[p] = cvt2(v1 - h1, v0 - h0);
            }
            size_t widx = (((size_t)(bb * HH + h) * HDIM + d) * NNODE + n0) >> 1;
            *(uint4*)&OutH[widx] = make_uint4(wh[0], wh[1], wh[2], wh[3]);
            *(uint4*)&OutL[widx] = make_uint4(wl[0], wl[1], wl[2], wl[3]);
        }
    } else {
        #pragma unroll
        for (int ii = 0; ii < 8; ii++) {
            float f0, f1, f2, f3;
            upk2(acc[ii][0], f0, f1);
            upk2(acc[ii][1], f2, f3);
            f0 = (f0 + b4.x) * scale; f1 = (f1 + b4.y) * scale;
            f2 = (f2 + b4.z) * scale; f3 = (f3 + b4.w) * scale;
            float h0 = bf16rt(f0), h1 = bf16rt(f1), h2 = bf16rt(f2), h3 = bf16rt(f3);
            int n = n0 + ii;
            size_t widx = ((size_t)(bb * HH + h) * NNODE + n) * (HDIM/2) + (cw >> 1);
            *(uint2*)&OutH[widx] = make_uint2(cvt2(h1, h0), cvt2(h3, h2));
            *(uint2*)&OutL[widx] = make_uint2(cvt2(f1 - h1, f0 - h0), cvt2(f3 - h3, f2 - h2));
        }
    }
}

// ---------------- O projection GEMM (fp32 out) ----------------
__global__ void __launch_bounds__(256) k_gemmO(const float* __restrict__ A, const float* __restrict__ W,
                       const float* __restrict__ bias, float* __restrict__ OutF) {
    __shared__ __align__(16) u64   As2[16][130];
    __shared__ __align__(16) float Ws[16][68];
    int tid = threadIdx.x;
    int tx = tid & 15;
    int rg = tid >> 4;
    int m0 = blockIdx.x * 128, c0 = blockIdx.y * 64;
    int lkk = tid & 15, lm = tid >> 4;

    u64 acc[8][2];
    #pragma unroll
    for (int i = 0; i < 8; i++) { acc[i][0] = 0ull; acc[i][1] = 0ull; }

    for (int k0 = 0; k0 < DDIM; k0 += 16) {
        #pragma unroll
        for (int rr = 0; rr < 8; rr++) {
            int m = lm + 16 * rr;
            float v = A[(size_t)(m0 + m) * DDIM + k0 + lkk];
            As2[lkk][m] = pk2(v, v);
        }
        #pragma unroll
        for (int rr = 0; rr < 4; rr++) {
            int c = lm + 16 * rr;
            Ws[lkk][c] = W[(size_t)(c0 + c) * DDIM + k0 + lkk];
        }
        __syncthreads();
        #pragma unroll
        for (int kk = 0; kk < 16; kk++) {
            float4 w4 = *(const float4*)&Ws[kk][tx * 4];
            u64 w01 = pk2(w4.x, w4.y), w23 = pk2(w4.z, w4.w);
            const u64* arow = &As2[kk][rg * 8];
            #pragma unroll
            for (int ii = 0; ii < 8; ii += 2) {
                ulonglong2 a2 = *(const ulonglong2*)&arow[ii];
                acc[ii][0]     = ffma2(a2.x, w01, acc[ii][0]);
                acc[ii][1]     = ffma2(a2.x, w23, acc[ii][1]);
                acc[ii + 1][0] = ffma2(a2.y, w01, acc[ii + 1][0]);
                acc[ii + 1][1] = ffma2(a2.y, w23, acc[ii + 1][1]);
            }
        }
        __syncthreads();
    }

    float4 b4 = *(const float4*)&bias[c0 + tx * 4];
    int c = c0 + tx * 4;
    #pragma unroll
    for (int ii = 0; ii < 8; ii++) {
        int m = m0 + rg * 8 + ii;
        float f0, f1, f2, f3;
        upk2(acc[ii][0], f0, f1);
        upk2(acc[ii][1], f2, f3);
        *(float4*)&OutF[(size_t)m * DDIM + c] =
            make_float4(f0 + b4.x, f1 + b4.y, f2 + b4.z, f3 + b4.w);
    }
}

// ---------------- fused masked attention + sparse_mask writeback ----------------
// block: 256 thr (8 warps), one (bh), 128 query rows. warp w owns rows 16w..16w+15.
// also writes outMask[bh, i0:i0+128, :] (bit->float), overlapping stores with MMA.
__global__ void __launch_bounds__(256) k_attn(float* __restrict__ outMask) {
    __shared__ __align__(16) u32 Ksh[128][20], Ksl[128][20];   // K bf16-pair words, padded
    __shared__ __align__(16) u32 Vth[32][68],  Vtl[32][68];    // V^T bf16-pair words, padded
    __shared__ __align__(16) u32 eW[128][4];                   // merged edge|col bits per row per 128-j tile

    int tid = threadIdx.x;
    int wp = tid >> 5, lane = tid & 31;
    int gid = lane >> 2, tig = lane & 3;
    int bh = blockIdx.y, b = bh >> 3, h = bh & 7;
    int i0 = blockIdx.x * 128;
    int rlo = wp * 16 + gid;          // local row in [0,128)

    const u32* gqh = (const u32*)g_Qh;
    const u32* gql = (const u32*)g_Ql;
    const uint4* gkh4 = (const uint4*)g_Kh;
    const uint4* gkl4 = (const uint4*)g_Kl;
    const uint4* gvh4 = (const uint4*)g_Vh;
    const uint4* gvl4 = (const uint4*)g_Vl;

    // Q A-fragments (scale already folded in)
    u32 qh[2][4], ql[2][4];
    {
        size_t blo = ((size_t)bh * NNODE + i0 + rlo) * 16;
        size_t bhi = blo + 8 * 16;
        #pragma unroll
        for (int kc = 0; kc < 2; kc++) {
            qh[kc][0] = gqh[blo + kc*8 + tig];
            qh[kc][1] = gqh[bhi + kc*8 + tig];
            qh[kc][2] = gqh[blo + kc*8 + tig + 4];
            qh[kc][3] = gqh[bhi + kc*8 + tig + 4];
            ql[kc][0] = gql[blo + kc*8 + tig];
            ql[kc][1] = gql[bhi + kc*8 + tig];
            ql[kc][2] = gql[blo + kc*8 + tig + 4];
            ql[kc][3] = gql[bhi + kc*8 + tig + 4];
        }
    }

    float oc[4][4];
    #pragma unroll
    for (int vt = 0; vt < 4; vt++)
        #pragma unroll
        for (int e = 0; e < 4; e++) oc[vt][e] = 0.0f;
    float zlo = 0.0f, zhi = 0.0f, slo = 0.0f, shi = 0.0f;

    // mask writeback mapping: thread -> (row = tid>>1, 64-col half = tid&1)
    int mrow = tid >> 1, mhalf = tid & 1;
    float4* mdst = (float4*)(outMask + ((size_t)bh * NNODE + i0 + mrow) * NNODE + mhalf * 64);

    for (int j0 = 0; j0 < NNODE; j0 += 128) {
        __syncthreads();
        // stage K hi/lo (uint4)
        for (int idx = tid; idx < 512; idx += 256) {
            int r = idx >> 2, w4 = (idx & 3) * 4;
            size_t gw = (((size_t)bh * NNODE + j0 + r) * 16 + w4) >> 2;
            *(uint4*)&Ksh[r][w4] = gkh4[gw];
            *(uint4*)&Ksl[r][w4] = gkl4[gw];
        }
        // stage V^T hi/lo (uint4)
        for (int idx = tid; idx < 512; idx += 256) {
            int d = idx >> 4, a4 = (idx & 15) * 4;
            size_t gw = (((size_t)bh * HDIM + d) * (NNODE/2) + (j0 >> 1) + a4) >> 2;
            *(uint4*)&Vth[d][a4] = gvh4[gw];
            *(uint4*)&Vtl[d][a4] = gvl4[gw];
        }
        // stage merged mask bits (uint4 per row)
        {
            int wb = j0 >> 5;
            uint4 cb = *(const uint4*)&g_colbits[b * NWRD + wb];
            for (int r = tid; r < 128; r += 256) {
                uint4 e4 = *(const uint4*)&g_edge[(size_t)(i0 + r) * NWRD + wb];
                eW[r][0] = e4.x | cb.x; eW[r][1] = e4.y | cb.y;
                eW[r][2] = e4.z | cb.z; eW[r][3] = e4.w | cb.w;
            }
        }
        __syncthreads();

        // ---- sparse_mask writeback for this 128x128 tile (overlaps with MMA below) ----
        {
            float4* mt = (float4*)((float*)mdst + j0);
            #pragma unroll
            for (int w = 0; w < 2; w++) {
                u32 bits = eW[mrow][mhalf * 2 + w];
                #pragma unroll
                for (int q = 0; q < 8; q++) {
                    float4 f;
                    f.x = (bits >> (q * 4 + 0)) & 1u ? 1.0f : 0.0f;
                    f.y = (bits >> (q * 4 + 1)) & 1u ? 1.0f : 0.0f;
                    f.z = (bits >> (q * 4 + 2)) & 1u ? 1.0f : 0.0f;
                    f.w = (bits >> (q * 4 + 3)) & 1u ? 1.0f : 0.0f;
                    mt[w * 8 + q] = f;
                }
            }
        }

        #pragma unroll 1
        for (int sub = 0; sub < 4; sub++) {
            // ---- S = Q K^T (3-term bf16) ----
            float sc[4][4];
            #pragma unroll
            for (int nt = 0; nt < 4; nt++)
                #pragma unroll
                for (int e = 0; e < 4; e++) sc[nt][e] = 0.0f;
            #pragma unroll
            for (int kc = 0; kc < 2; kc++)
                #pragma unroll
                for (int nt = 0; nt < 4; nt++) {
                    int jr = sub * 32 + nt * 8 + gid;
                    u32 b0h = Ksh[jr][kc*8 + tig], b1h = Ksh[jr][kc*8 + tig + 4];
                    u32 b0l = Ksl[jr][kc*8 + tig], b1l = Ksl[jr][kc*8 + tig + 4];
                    mma16816(sc[nt], qh[kc], b0h, b1h);
                    mma16816(sc[nt], ql[kc], b0h, b1h);
                    mma16816(sc[nt], qh[kc], b0l, b1l);
                }
            // ---- exp + mask + row sums ----
            u32 wlo = eW[wp * 16 + gid][sub];
            u32 whi = eW[wp * 16 + gid + 8][sub];
            float pm[4][4];
            #pragma unroll
            for (int nt = 0; nt < 4; nt++) {
                float p0 = __expf(sc[nt][0]);
                float p1 = __expf(sc[nt][1]);
                float p2 = __expf(sc[nt][2]);
                float p3 = __expf(sc[nt][3]);
                int bp = nt * 8 + tig * 2;
                float m0 = ((wlo >> bp) & 1u) ? p0 : 0.0f;
                float m1 = ((wlo >> (bp + 1)) & 1u) ? p1 : 0.0f;
                float m2 = ((whi >> bp) & 1u) ? p2 : 0.0f;
                float m3 = ((whi >> (bp + 1)) & 1u) ? p3 : 0.0f;
                zlo += p0 + p1; zhi += p2 + p3;
                slo += m0 + m1; shi += m2 + m3;
                pm[nt][0] = m0; pm[nt][1] = m1; pm[nt][2] = m2; pm[nt][3] = m3;
            }
            // ---- P -> bf16 hi/lo A-fragments (C layout == A layout) ----
            u32 ph[2][4], pl[2][4];
            #pragma unroll
            for (int kc = 0; kc < 2; kc++) {
                int na = kc * 2, nb = kc * 2 + 1;
                float h00 = bf16rt(pm[na][0]), h01 = bf16rt(pm[na][1]);
                float h02 = bf16rt(pm[na][2]), h03 = bf16rt(pm[na][3]);
                float h10 = bf16rt(pm[nb][0]), h11 = bf16rt(pm[nb][1]);
                float h12 = bf16rt(pm[nb][2]), h13 = bf16rt(pm[nb][3]);
                ph[kc][0] = cvt2(h01, h00);
                ph[kc][1] = cvt2(h03, h02);
                ph[kc][2] = cvt2(h11, h10);
                ph[kc][3] = cvt2(h13, h12);
                pl[kc][0] = cvt2(pm[na][1] - h01, pm[na][0] - h00);
                pl[kc][1] = cvt2(pm[na][3] - h03, pm[na][2] - h02);
                pl[kc][2] = cvt2(pm[nb][1] - h11, pm[nb][0] - h10);
                pl[kc][3] = cvt2(pm[nb][3] - h13, pm[nb][2] - h12);
            }
            // ---- O += P V (3-term bf16) ----
            #pragma unroll
            for (int kc = 0; kc < 2; kc++)
                #pragma unroll
                for (int vt = 0; vt < 4; vt++) {
                    int d = vt * 8 + gid;
                    int wj = sub * 16 + kc * 8 + tig;
                    u32 b0h = Vth[d][wj], b1h = Vth[d][wj + 4];
                    u32 b0l = Vtl[d][wj], b1l = Vtl[d][wj + 4];
                    mma16816(oc[vt], ph[kc], b0h, b1h);
                    mma16816(oc[vt], pl[kc], b0h, b1h);
                    mma16816(oc[vt], ph[kc], b0l, b1l);
                }
        }
    }

    // reduce Z/S across the quad (lanes with same row)
    #pragma unroll
    for (int o = 1; o <= 2; o <<= 1) {
        zlo += __shfl_xor_sync(0xffffffffu, zlo, o);
        zhi += __shfl_xor_sync(0xffffffffu, zhi, o);
        slo += __shfl_xor_sync(0xffffffffu, slo, o);
        shi += __shfl_xor_sync(0xffffffffu, shi, o);
    }
    float invlo = 1.0f / (slo + 1e-8f * zlo);
    float invhi = 1.0f / (shi + 1e-8f * zhi);

    int nlo = i0 + wp * 16 + gid;
    int nhi = nlo + 8;
    size_t olo = ((size_t)(b * NNODE + nlo)) * DDIM + h * HDIM;
    size_t ohi = ((size_t)(b * NNODE + nhi)) * DDIM + h * HDIM;
    #pragma unroll
    for (int vt = 0; vt < 4; vt++) {
        int d = vt * 8 + tig * 2;
        *(float2*)&g_attn[olo + d] = make_float2(oc[vt][0] * invlo, oc[vt][1] * invlo);
        *(float2*)&g_attn[ohi + d] = make_float2(oc[vt][2] * invhi, oc[vt][3] * invhi);
    }
}

// ---------------- launch (single stream; graph-capturable, no resource creation) ----------------
extern "C" void kernel_launch(void* const* d_in, const int* in_sizes, int n_in,
                              void* d_out, int out_size) {
    (void)in_sizes; (void)n_in; (void)out_size;
    const float* x   = (const float*)d_in[0];
    const int*   ei  = (const int*)  d_in[1];
    const float* qw  = (const float*)d_in[2];
    const float* qb  = (const float*)d_in[3];
    const float* kw  = (const float*)d_in[4];
    const float* kb  = (const float*)d_in[5];
    const float* vw  = (const float*)d_in[6];
    const float* vb  = (const float*)d_in[7];
    const float* ow  = (const float*)d_in[8];
    const float* ob  = (const float*)d_in[9];
    const float* g1w = (const float*)d_in[10];
    const float* g1b = (const float*)d_in[11];
    const float* g2w = (const float*)d_in[12];
    const float* g2b = (const float*)d_in[13];

    float* out = (float*)d_out;
    float* outMask = out + (size_t)BB * NNODE * DDIM;

    u32 *pQh, *pQl, *pKh, *pKl, *pVh, *pVl;
    float* pAttn;
    cudaGetSymbolAddress((void**)&pQh, g_Qh);
    cudaGetSymbolAddress((void**)&pQl, g_Ql);
    cudaGetSymbolAddress((void**)&pKh, g_Kh);
    cudaGetSymbolAddress((void**)&pKl, g_Kl);
    cudaGetSymbolAddress((void**)&pVh, g_Vh);
    cudaGetSymbolAddress((void**)&pVl, g_Vl);
    cudaGetSymbolAddress((void**)&pAttn, g_attn);

    const float qscale = 0.17677669529663687f;  // 1/sqrt(32)

    k_zero<<<512, 256>>>();
    k_scatter<<<EEDGE / 256, 256>>>(ei);
    k_topo<<<BB * NNODE / 8, 128>>>(x, g1w, g1b, g2w, g2b);
    k_topk<<<BB, 256>>>();

    dim3 qkvgrid(BB * NNODE / 128, DDIM / 64, 3);
    k_gemmQKV<<<qkvgrid, 256>>>(x, qw, qb, kw, kb, vw, vb,
                                pQh, pQl, pKh, pKl, pVh, pVl, qscale);

    k_attn<<<dim3(NNODE / 128, BB * HH), 256>>>(outMask);

    dim3 ogrid(BB * NNODE / 128, DDIM / 64);
    k_gemmO<<<ogrid, 256>>>(pAttn, ow, ob, out);
}

// round 6
// speedup vs baseline: 2.4185x; 1.2468x over previous
#include <cuda_runtime.h>
#include <cuda_bf16.h>
#include <cstdint>
#include <cstddef>

#define BB 2
#define NNODE 2048
#define DDIM 256
#define HH 8
#define HDIM 32
#define EEDGE 65536
#define KTOP 1024
#define NWRD (NNODE/32)   // 64 u32 words per adjacency row

typedef unsigned u32;
typedef unsigned long long u64;

// ---------------- packed f32x2 helpers ----------------
__device__ __forceinline__ u64 ffma2(u64 a, u64 b, u64 c) {
    u64 d; asm("fma.rn.f32x2 %0, %1, %2, %3;" : "=l"(d) : "l"(a), "l"(b), "l"(c)); return d;
}
__device__ __forceinline__ u64 pk2(float lo, float hi) {
    u64 d; asm("mov.b64 %0, {%1, %2};" : "=l"(d) : "f"(lo), "f"(hi)); return d;
}
__device__ __forceinline__ void upk2(u64 v, float& lo, float& hi) {
    asm("mov.b64 {%0, %1}, %2;" : "=f"(lo), "=f"(hi) : "l"(v));
}
// pack two fp32 -> bf16x2 (hi goes to upper 16 bits)
__device__ __forceinline__ u32 cvt2(float hi, float lo) {
    u32 r; asm("cvt.rn.bf16x2.f32 %0, %1, %2;" : "=r"(r) : "f"(hi), "f"(lo)); return r;
}
__device__ __forceinline__ float bf16rt(float x) {
    return __bfloat162float(__float2bfloat16_rn(x));
}
// mma.sync m16n8k16 bf16 row.col, fp32 accumulate
__device__ __forceinline__ void mma16816(float c[4], const u32 a[4], u32 b0, u32 b1) {
    asm volatile(
        "mma.sync.aligned.m16n8k16.row.col.f32.bf16.bf16.f32 "
        "{%0,%1,%2,%3},{%4,%5,%6,%7},{%8,%9},{%0,%1,%2,%3};"
        : "+f"(c[0]), "+f"(c[1]), "+f"(c[2]), "+f"(c[3])
        : "r"(a[0]), "r"(a[1]), "r"(a[2]), "r"(a[3]), "r"(b0), "r"(b1));
}

// ---------------- scratch (device globals) ----------------
__device__ float g_topo[BB*NNODE];
__device__ u32   g_edge[NNODE*NWRD];
__device__ u32   g_colbits[BB*NWRD];
// bf16 hi/lo operand arrays. Q/K layout [bh][n][32]; V layout [bh][d][n] (transposed)
__device__ __nv_bfloat16 g_Qh[(size_t)BB*HH*NNODE*HDIM];
__device__ __nv_bfloat16 g_Ql[(size_t)BB*HH*NNODE*HDIM];
__device__ __nv_bfloat16 g_Kh[(size_t)BB*HH*NNODE*HDIM];
__device__ __nv_bfloat16 g_Kl[(size_t)BB*HH*NNODE*HDIM];
__device__ __nv_bfloat16 g_Vh[(size_t)BB*HH*NNODE*HDIM];
__device__ __nv_bfloat16 g_Vl[(size_t)BB*HH*NNODE*HDIM];
__device__ float g_attn[(size_t)BB*NNODE*DDIM];

// ---------------- zero edge bits + colbits ----------------
__global__ void k_zero() {
    int i = blockIdx.x * blockDim.x + threadIdx.x;
    if (i < NNODE*NWRD) g_edge[i] = 0u;
    if (i < BB*NWRD)    g_colbits[i] = 0u;
}

// ---------------- scatter edges into bitmask ----------------
__global__ void k_scatter(const int* __restrict__ ei) {
    int e = blockIdx.x * blockDim.x + threadIdx.x;
    if (e >= EEDGE) return;
    int r = ei[e];
    int c = ei[EEDGE + e];
    atomicOr(&g_edge[r * NWRD + (c >> 5)], 1u << (c & 31));
}

// ---------------- topo scores (f32x2 packed) ----------------
__global__ void __launch_bounds__(128) k_topo(const float* __restrict__ x,
                       const float* __restrict__ g1w, const float* __restrict__ g1b,
                       const float* __restrict__ g2w, const float* __restrict__ g2b) {
    __shared__ __align__(16) float xs[8][DDIM];
    __shared__ float rs[8][4];
    int t = threadIdx.x;
    int base = blockIdx.x * 8;

    const float4* xv = (const float4*)(x + (size_t)base * DDIM);
    float4* xsv = (float4*)&xs[0][0];
    #pragma unroll
    for (int r = 0; r < 4; r++) xsv[t + r * 128] = xv[t + r * 128];
    __syncthreads();

    u64 acc[8];
    #pragma unroll
    for (int nn = 0; nn < 8; nn++) acc[nn] = 0ull;

    const ulonglong2* wrow = (const ulonglong2*)(g1w + (size_t)t * DDIM);
    #pragma unroll 4
    for (int k4 = 0; k4 < DDIM/4; k4++) {
        ulonglong2 wv = wrow[k4];
        #pragma unroll
        for (int nn = 0; nn < 8; nn++) {
            ulonglong2 xp = ((const ulonglong2*)xs[nn])[k4];
            acc[nn] = ffma2(wv.x, xp.x, acc[nn]);
            acc[nn] = ffma2(wv.y, xp.y, acc[nn]);
        }
    }
    float b1 = g1b[t];
    float w2s = g2w[t];
    float res[8];
    #pragma unroll
    for (int nn = 0; nn < 8; nn++) {
        float lo, hi; upk2(acc[nn], lo, hi);
        float h = fmaxf(lo + hi + b1, 0.0f);
        res[nn] = h * w2s;
    }
    int lane = t & 31, wrp = t >> 5;
    #pragma unroll
    for (int nn = 0; nn < 8; nn++) {
        float v = res[nn];
        #pragma unroll
        for (int o = 16; o > 0; o >>= 1) v += __shfl_down_sync(0xffffffffu, v, o);
        if (lane == 0) rs[nn][wrp] = v;
    }
    __syncthreads();
    if (t < 8) {
        float v = rs[t][0] + rs[t][1] + rs[t][2] + rs[t][3];
        g_topo[base + t] = v + g2b[0];
    }
}

// ---------------- exact top-k: radix select with parallel threshold find ----------------
__global__ void __launch_bounds__(256) k_topk() {
    __shared__ u32 keys[NNODE];
    __shared__ u32 hist[256];
    __shared__ u32 sb[256];
    __shared__ u32 scn[256];
    __shared__ u32 sh_prefix, sh_remain;
    int b = blockIdx.x;
    int t = threadIdx.x;  // 256 threads

    for (int i = t; i < NNODE; i += 256) {
        u32 u = __float_as_uint(g_topo[b * NNODE + i]);
        u = (u & 0x80000000u) ? ~u : (u | 0x80000000u);  // monotone ascending
        keys[i] = u;
    }
    u32 prefix = 0, remain = KTOP;
    __syncthreads();

    for (int shift = 24; shift >= 0; shift -= 8) {
        hist[t] = 0;
        __syncthreads();
        for (int i = t; i < NNODE; i += 256) {
            u32 k = keys[i];
            bool in_group = (shift == 24) || ((k >> (shift + 8)) == prefix);
            if (in_group) atomicAdd(&hist[(k >> shift) & 255], 1u);
        }
        __syncthreads();
        // parallel inclusive SUFFIX sum: sb[v] = sum_{u>=v} hist[u]
        sb[t] = hist[t];
        __syncthreads();
        for (int ofs = 1; ofs < 256; ofs <<= 1) {
            u32 add = (t + ofs < 256) ? sb[t + ofs] : 0u;
            __syncthreads();
            sb[t] += add;
            __syncthreads();
        }
        u32 above = (t == 255) ? 0u : sb[t + 1];
        if (sb[t] >= remain && above < remain) {
            sh_prefix = (prefix << 8) | (u32)t;
            sh_remain = remain - above;
        }
        __syncthreads();
        prefix = sh_prefix;
        remain = sh_remain;
        __syncthreads();
    }
    u32 T = prefix;  // KTOP-th largest key; take `remain` of the ==T set in index order

    u32 cnt = 0;
    #pragma unroll
    for (int u = 0; u < 8; u++) if (keys[t * 8 + u] == T) cnt++;
    scn[t] = cnt;
    __syncthreads();
    for (int ofs = 1; ofs < 256; ofs <<= 1) {
        u32 v = scn[t];
        u32 add = (t >= ofs) ? scn[t - ofs] : 0u;
        __syncthreads();
        scn[t] = v + add;
        __syncthreads();
    }
    u32 taken = scn[t] - cnt;
    u32 byte = 0;
    #pragma unroll
    for (int u = 0; u < 8; u++) {
        u32 k = keys[t * 8 + u];
        bool m = false;
        if (k > T) m = true;
        else if (k == T) { if (taken < remain) m = true; taken++; }
        if (m) byte |= (1u << u);
    }
    atomicOr(&g_colbits[b * NWRD + (t >> 2)], byte << ((t & 3) * 8));
}

// ---------------- fused QKV GEMM (f32x2 core), blockIdx.z selects Q/K/V ----------------
// z=0: Q -> bf16 hi/lo [bh][n][32], scaled by 1/sqrt(hd)
// z=1: K -> bf16 hi/lo [bh][n][32]
// z=2: V -> bf16 hi/lo TRANSPOSED [bh][d][n]
__global__ void __launch_bounds__(256) k_gemmQKV(
        const float* __restrict__ A,
        const float* __restrict__ qw, const float* __restrict__ qb,
        const float* __restrict__ kw, const float* __restrict__ kb,
        const float* __restrict__ vw, const float* __restrict__ vb,
        u32* __restrict__ Qh, u32* __restrict__ Ql,
        u32* __restrict__ Kh, u32* __restrict__ Kl,
        u32* __restrict__ Vh, u32* __restrict__ Vl, float qscale) {
    __shared__ __align__(16) u64   As2[16][130];
    __shared__ __align__(16) float Ws[16][68];
    int mode = blockIdx.z;
    const float* W    = (mode == 0) ? qw : (mode == 1) ? kw : vw;
    const float* bias = (mode == 0) ? qb : (mode == 1) ? kb : vb;
    u32* OutH = (mode == 0) ? Qh : (mode == 1) ? Kh : Vh;
    u32* OutL = (mode == 0) ? Ql : (mode == 1) ? Kl : Vl;
    float scale = (mode == 0) ? qscale : 1.0f;

    int tid = threadIdx.x;
    int tx = tid & 15;       // col group: cols c0 + tx*4 + {0..3}
    int rg = tid >> 4;       // row group: rows m0 + rg*8 + {0..7}
    int m0 = blockIdx.x * 128, c0 = blockIdx.y * 64;
    int lkk = tid & 15, lm = tid >> 4;

    u64 acc[8][2];
    #pragma unroll
    for (int i = 0; i < 8; i++) { acc[i][0] = 0ull; acc[i][1] = 0ull; }

    for (int k0 = 0; k0 < DDIM; k0 += 16) {
        #pragma unroll
        for (int rr = 0; rr < 8; rr++) {
            int m = lm + 16 * rr;
            float v = A[(size_t)(m0 + m) * DDIM + k0 + lkk];
            As2[lkk][m] = pk2(v, v);
        }
        #pragma unroll
        for (int rr = 0; rr < 4; rr++) {
            int c = lm + 16 * rr;
            Ws[lkk][c] = W[(size_t)(c0 + c) * DDIM + k0 + lkk];
        }
        __syncthreads();
        #pragma unroll
        for (int kk = 0; kk < 16; kk++) {
            float4 w4 = *(const float4*)&Ws[kk][tx * 4];
            u64 w01 = pk2(w4.x, w4.y), w23 = pk2(w4.z, w4.w);
            const u64* arow = &As2[kk][rg * 8];
            #pragma unroll
            for (int ii = 0; ii < 8; ii += 2) {
                ulonglong2 a2 = *(const ulonglong2*)&arow[ii];
                acc[ii][0]     = ffma2(a2.x, w01, acc[ii][0]);
                acc[ii][1]     = ffma2(a2.x, w23, acc[ii][1]);
                acc[ii + 1][0] = ffma2(a2.y, w01, acc[ii + 1][0]);
                acc[ii + 1][1] = ffma2(a2.y, w23, acc[ii + 1][1]);
            }
        }
        __syncthreads();
    }

    float4 b4 = *(const float4*)&bias[c0 + tx * 4];
    int c = c0 + tx * 4;                 // 4 consecutive cols (same head)
    int h = (c >> 5) & 7, cw = c & 31;
    int bb = m0 >> 11;                   // m0 multiple of 128, no batch straddle
    int n0 = (m0 & 2047) + rg * 8;

    if (mode == 2) {
        float vals[8][4];
        #pragma unroll
        for (int ii = 0; ii < 8; ii++) {
            float f0, f1, f2, f3;
            upk2(acc[ii][0], f0, f1);
            upk2(acc[ii][1], f2, f3);
            vals[ii][0] = f0 + b4.x; vals[ii][1] = f1 + b4.y;
            vals[ii][2] = f2 + b4.z; vals[ii][3] = f3 + b4.w;
        }
        #pragma unroll
        for (int jj = 0; jj < 4; jj++) {
            int d = cw + jj;
            u32 wh[4], wl[4];
            #pragma unroll
            for (int p = 0; p < 4; p++) {
                float v0 = vals[2*p][jj],   v1 = vals[2*p+1][jj];
                float h0 = bf16rt(v0), h1 = bf16rt(v1);
                wh[p] = cvt2(h1, h0);
                wl[p] = cvt2(v1 - h1, v0 - h0);
            }
            size_t widx = (((size_t)(bb * HH + h) * HDIM + d) * NNODE + n0) >> 1;
            *(uint4*)&OutH[widx] = make_uint4(wh[0], wh[1], wh[2], wh[3]);
            *(uint4*)&OutL[widx] = make_uint4(wl[0], wl[1], wl[2], wl[3]);
        }
    } else {
        #pragma unroll
        for (int ii = 0; ii < 8; ii++) {
            float f0, f1, f2, f3;
            upk2(acc[ii][0], f0, f1);
            upk2(acc[ii][1], f2, f3);
            f0 = (f0 + b4.x) * scale; f1 = (f1 + b4.y) * scale;
            f2 = (f2 + b4.z) * scale; f3 = (f3 + b4.w) * scale;
            float h0 = bf16rt(f0), h1 = bf16rt(f1), h2 = bf16rt(f2), h3 = bf16rt(f3);
            int n = n0 + ii;
            size_t widx = ((size_t)(bb * HH + h) * NNODE + n) * (HDIM/2) + (cw >> 1);
            *(uint2*)&OutH[widx] = make_uint2(cvt2(h1, h0), cvt2(h3, h2));
            *(uint2*)&OutL[widx] = make_uint2(cvt2(f1 - h1, f0 - h0), cvt2(f3 - h3, f2 - h2));
        }
    }
}

// ---------------- O projection GEMM (fp32 out) ----------------
__global__ void __launch_bounds__(256) k_gemmO(const float* __restrict__ A, const float* __restrict__ W,
                       const float* __restrict__ bias, float* __restrict__ OutF) {
    __shared__ __align__(16) u64   As2[16][130];
    __shared__ __align__(16) float Ws[16][68];
    int tid = threadIdx.x;
    int tx = tid & 15;
    int rg = tid >> 4;
    int m0 = blockIdx.x * 128, c0 = blockIdx.y * 64;
    int lkk = tid & 15, lm = tid >> 4;

    u64 acc[8][2];
    #pragma unroll
    for (int i = 0; i < 8; i++) { acc[i][0] = 0ull; acc[i][1] = 0ull; }

    for (int k0 = 0; k0 < DDIM; k0 += 16) {
        #pragma unroll
        for (int rr = 0; rr < 8; rr++) {
            int m = lm + 16 * rr;
            float v = A[(size_t)(m0 + m) * DDIM + k0 + lkk];
            As2[lkk][m] = pk2(v, v);
        }
        #pragma unroll
        for (int rr = 0; rr < 4; rr++) {
            int c = lm + 16 * rr;
            Ws[lkk][c] = W[(size_t)(c0 + c) * DDIM + k0 + lkk];
        }
        __syncthreads();
        #pragma unroll
        for (int kk = 0; kk < 16; kk++) {
            float4 w4 = *(const float4*)&Ws[kk][tx * 4];
            u64 w01 = pk2(w4.x, w4.y), w23 = pk2(w4.z, w4.w);
            const u64* arow = &As2[kk][rg * 8];
            #pragma unroll
            for (int ii = 0; ii < 8; ii += 2) {
                ulonglong2 a2 = *(const ulonglong2*)&arow[ii];
                acc[ii][0]     = ffma2(a2.x, w01, acc[ii][0]);
                acc[ii][1]     = ffma2(a2.x, w23, acc[ii][1]);
                acc[ii + 1][0] = ffma2(a2.y, w01, acc[ii + 1][0]);
                acc[ii + 1][1] = ffma2(a2.y, w23, acc[ii + 1][1]);
            }
        }
        __syncthreads();
    }

    float4 b4 = *(const float4*)&bias[c0 + tx * 4];
    int c = c0 + tx * 4;
    #pragma unroll
    for (int ii = 0; ii < 8; ii++) {
        int m = m0 + rg * 8 + ii;
        float f0, f1, f2, f3;
        upk2(acc[ii][0], f0, f1);
        upk2(acc[ii][1], f2, f3);
        *(float4*)&OutF[(size_t)m * DDIM + c] =
            make_float4(f0 + b4.x, f1 + b4.y, f2 + b4.z, f3 + b4.w);
    }
}

// ---------------- fused masked attention + coalesced sparse_mask writeback ----------------
// block: 256 thr (8 warps), one (bh), 128 query rows. warp w owns rows 16w..16w+15.
__global__ void __launch_bounds__(256) k_attn(float* __restrict__ outMask) {
    __shared__ __align__(16) u32 Ksh[128][20], Ksl[128][20];   // K bf16-pair words, padded
    __shared__ __align__(16) u32 Vth[32][68],  Vtl[32][68];    // V^T bf16-pair words, padded
    __shared__ __align__(16) u32 eW[128][4];                   // merged edge|col bits per row per 128-j tile

    int tid = threadIdx.x;
    int wp = tid >> 5, lane = tid & 31;
    int gid = lane >> 2, tig = lane & 3;
    int bh = blockIdx.y, b = bh >> 3, h = bh & 7;
    int i0 = blockIdx.x * 128;
    int rlo = wp * 16 + gid;          // local row in [0,128)

    const u32* gqh = (const u32*)g_Qh;
    const u32* gql = (const u32*)g_Ql;
    const uint4* gkh4 = (const uint4*)g_Kh;
    const uint4* gkl4 = (const uint4*)g_Kl;
    const uint4* gvh4 = (const uint4*)g_Vh;
    const uint4* gvl4 = (const uint4*)g_Vl;

    // Q A-fragments (scale already folded in)
    u32 qh[2][4], ql[2][4];
    {
        size_t blo = ((size_t)bh * NNODE + i0 + rlo) * 16;
        size_t bhi = blo + 8 * 16;
        #pragma unroll
        for (int kc = 0; kc < 2; kc++) {
            qh[kc][0] = gqh[blo + kc*8 + tig];
            qh[kc][1] = gqh[bhi + kc*8 + tig];
            qh[kc][2] = gqh[blo + kc*8 + tig + 4];
            qh[kc][3] = gqh[bhi + kc*8 + tig + 4];
            ql[kc][0] = gql[blo + kc*8 + tig];
            ql[kc][1] = gql[bhi + kc*8 + tig];
            ql[kc][2] = gql[blo + kc*8 + tig + 4];
            ql[kc][3] = gql[bhi + kc*8 + tig + 4];
        }
    }

    float oc[4][4];
    #pragma unroll
    for (int vt = 0; vt < 4; vt++)
        #pragma unroll
        for (int e = 0; e < 4; e++) oc[vt][e] = 0.0f;
    float slo = 0.0f, shi = 0.0f;

    for (int j0 = 0; j0 < NNODE; j0 += 128) {
        __syncthreads();
        // stage K hi/lo (uint4)
        for (int idx = tid; idx < 512; idx += 256) {
            int r = idx >> 2, w4 = (idx & 3) * 4;
            size_t gw = (((size_t)bh * NNODE + j0 + r) * 16 + w4) >> 2;
            *(uint4*)&Ksh[r][w4] = gkh4[gw];
            *(uint4*)&Ksl[r][w4] = gkl4[gw];
        }
        // stage V^T hi/lo (uint4)
        for (int idx = tid; idx < 512; idx += 256) {
            int d = idx >> 4, a4 = (idx & 15) * 4;
            size_t gw = (((size_t)bh * HDIM + d) * (NNODE/2) + (j0 >> 1) + a4) >> 2;
            *(uint4*)&Vth[d][a4] = gvh4[gw];
            *(uint4*)&Vtl[d][a4] = gvl4[gw];
        }
        // stage merged mask bits (uint4 per row)
        {
            int wb = j0 >> 5;
            uint4 cb = *(const uint4*)&g_colbits[b * NWRD + wb];
            for (int r = tid; r < 128; r += 256) {
                uint4 e4 = *(const uint4*)&g_edge[(size_t)(i0 + r) * NWRD + wb];
                eW[r][0] = e4.x | cb.x; eW[r][1] = e4.y | cb.y;
                eW[r][2] = e4.z | cb.z; eW[r][3] = e4.w | cb.w;
            }
        }
        __syncthreads();

        // ---- coalesced sparse_mask writeback for this 128x128 tile ----
        // warp instr: 32 lanes x float4 = 512 contiguous bytes in one row
        {
            #pragma unroll
            for (int rr = 0; rr < 16; rr++) {
                int r = wp + rr * 8;
                u32 bits = eW[r][lane >> 3];
                int bo = (lane & 7) * 4;
                float4 f;
                f.x = (bits >> (bo + 0)) & 1u ? 1.0f : 0.0f;
                f.y = (bits >> (bo + 1)) & 1u ? 1.0f : 0.0f;
                f.z = (bits >> (bo + 2)) & 1u ? 1.0f : 0.0f;
                f.w = (bits >> (bo + 3)) & 1u ? 1.0f : 0.0f;
                __stcs((float4*)(outMask + ((size_t)bh * NNODE + i0 + r) * NNODE + j0) + lane, f);
            }
        }

        #pragma unroll 1
        for (int sub = 0; sub < 4; sub++) {
            // ---- S = Q K^T (3-term bf16) ----
            float sc[4][4];
            #pragma unroll
            for (int nt = 0; nt < 4; nt++)
                #pragma unroll
                for (int e = 0; e < 4; e++) sc[nt][e] = 0.0f;
            #pragma unroll
            for (int kc = 0; kc < 2; kc++)
                #pragma unroll
                for (int nt = 0; nt < 4; nt++) {
                    int jr = sub * 32 + nt * 8 + gid;
                    u32 b0h = Ksh[jr][kc*8 + tig], b1h = Ksh[jr][kc*8 + tig + 4];
                    u32 b0l = Ksl[jr][kc*8 + tig], b1l = Ksl[jr][kc*8 + tig + 4];
                    mma16816(sc[nt], qh[kc], b0h, b1h);
                    mma16816(sc[nt], ql[kc], b0h, b1h);
                    mma16816(sc[nt], qh[kc], b0l, b1l);
                }
            // ---- exp + mask + row sums (Z dropped: 1e-8*Z term is <2e-8 relative) ----
            u32 wlo = eW[wp * 16 + gid][sub];
            u32 whi = eW[wp * 16 + gid + 8][sub];
            float pm[4][4];
            #pragma unroll
            for (int nt = 0; nt < 4; nt++) {
                float p0 = __expf(sc[nt][0]);
                float p1 = __expf(sc[nt][1]);
                float p2 = __expf(sc[nt][2]);
                float p3 = __expf(sc[nt][3]);
                int bp = nt * 8 + tig * 2;
                float m0 = ((wlo >> bp) & 1u) ? p0 : 0.0f;
                float m1 = ((wlo >> (bp + 1)) & 1u) ? p1 : 0.0f;
                float m2 = ((whi >> bp) & 1u) ? p2 : 0.0f;
                float m3 = ((whi >> (bp + 1)) & 1u) ? p3 : 0.0f;
                slo += m0 + m1; shi += m2 + m3;
                pm[nt][0] = m0; pm[nt][1] = m1; pm[nt][2] = m2; pm[nt][3] = m3;
            }
            // ---- P -> bf16 hi/lo A-fragments (C layout == A layout) ----
            u32 ph[2][4], pl[2][4];
            #pragma unroll
            for (int kc = 0; kc < 2; kc++) {
                int na = kc * 2, nb = kc * 2 + 1;
                float h00 = bf16rt(pm[na][0]), h01 = bf16rt(pm[na][1]);
                float h02 = bf16rt(pm[na][2]), h03 = bf16rt(pm[na][3]);
                float h10 = bf16rt(pm[nb][0]), h11 = bf16rt(pm[nb][1]);
                float h12 = bf16rt(pm[nb][2]), h13 = bf16rt(pm[nb][3]);
                ph[kc][0] = cvt2(h01, h00);
                ph[kc][1] = cvt2(h03, h02);
                ph[kc][2] = cvt2(h11, h10);
                ph[kc][3] = cvt2(h13, h12);
                pl[kc][0] = cvt2(pm[na][1] - h01, pm[na][0] - h00);
                pl[kc][1] = cvt2(pm[na][3] - h03, pm[na][2] - h02);
                pl[kc][2] = cvt2(pm[nb][1] - h11, pm[nb][0] - h10);
                pl[kc][3] = cvt2(pm[nb][3] - h13, pm[nb][2] - h12);
            }
            // ---- O += P V (3-term bf16) ----
            #pragma unroll
            for (int kc = 0; kc < 2; kc++)
                #pragma unroll
                for (int vt = 0; vt < 4; vt++) {
                    int d = vt * 8 + gid;
                    int wj = sub * 16 + kc * 8 + tig;
                    u32 b0h = Vth[d][wj], b1h = Vth[d][wj + 4];
                    u32 b0l = Vtl[d][wj], b1l = Vtl[d][wj + 4];
                    mma16816(oc[vt], ph[kc], b0h, b1h);
                    mma16816(oc[vt], pl[kc], b0h, b1h);
                    mma16816(oc[vt], ph[kc], b0l, b1l);
                }
        }
    }

    // reduce S across the quad (lanes with same row)
    #pragma unroll
    for (int o = 1; o <= 2; o <<= 1) {
        slo += __shfl_xor_sync(0xffffffffu, slo, o);
        shi += __shfl_xor_sync(0xffffffffu, shi, o);
    }
    float invlo = 1.0f / slo;
    float invhi = 1.0f / shi;

    int nlo = i0 + wp * 16 + gid;
    int nhi = nlo + 8;
    size_t olo = ((size_t)(b * NNODE + nlo)) * DDIM + h * HDIM;
    size_t ohi = ((size_t)(b * NNODE + nhi)) * DDIM + h * HDIM;
    #pragma unroll
    for (int vt = 0; vt < 4; vt++) {
        int d = vt * 8 + tig * 2;
        *(float2*)&g_attn[olo + d] = make_float2(oc[vt][0] * invlo, oc[vt][1] * invlo);
        *(float2*)&g_attn[ohi + d] = make_float2(oc[vt][2] * invhi, oc[vt][3] * invhi);
    }
}

// ---------------- launch (single stream; graph-capturable) ----------------
extern "C" void kernel_launch(void* const* d_in, const int* in_sizes, int n_in,
                              void* d_out, int out_size) {
    (void)in_sizes; (void)n_in; (void)out_size;
    const float* x   = (const float*)d_in[0];
    const int*   ei  = (const int*)  d_in[1];
    const float* qw  = (const float*)d_in[2];
    const float* qb  = (const float*)d_in[3];
    const float* kw  = (const float*)d_in[4];
    const float* kb  = (const float*)d_in[5];
    const float* vw  = (const float*)d_in[6];
    const float* vb  = (const float*)d_in[7];
    const float* ow  = (const float*)d_in[8];
    const float* ob  = (const float*)d_in[9];
    const float* g1w = (const float*)d_in[10];
    const float* g1b = (const float*)d_in[11];
    const float* g2w = (const float*)d_in[12];
    const float* g2b = (const float*)d_in[13];

    float* out = (float*)d_out;
    float* outMask = out + (size_t)BB * NNODE * DDIM;

    u32 *pQh, *pQl, *pKh, *pKl, *pVh, *pVl;
    float* pAttn;
    cudaGetSymbolAddress((void**)&pQh, g_Qh);
    cudaGetSymbolAddress((void**)&pQl, g_Ql);
    cudaGetSymbolAddress((void**)&pKh, g_Kh);
    cudaGetSymbolAddress((void**)&pKl, g_Kl);
    cudaGetSymbolAddress((void**)&pVh, g_Vh);
    cudaGetSymbolAddress((void**)&pVl, g_Vl);
    cudaGetSymbolAddress((void**)&pAttn, g_attn);

    const float qscale = 0.17677669529663687f;  // 1/sqrt(32)

    k_zero<<<512, 256>>>();
    k_scatter<<<EEDGE / 256, 256>>>(ei);
    k_topo<<<BB * NNODE / 8, 128>>>(x, g1w, g1b, g2w, g2b);
    k_topk<<<BB, 256>>>();

    dim3 qkvgrid(BB * NNODE / 128, DDIM / 64, 3);
    k_gemmQKV<<<qkvgrid, 256>>>(x, qw, qb, kw, kb, vw, vb,
                                pQh, pQl, pKh, pKl, pVh, pVl, qscale);

    k_attn<<<dim3(NNODE / 128, BB * HH), 256>>>(outMask);

    dim3 ogrid(BB * NNODE / 128, DDIM / 64);
    k_gemmO<<<ogrid, 256>>>(pAttn, ow, ob, out);
}

// round 7
// speedup vs baseline: 2.5915x; 1.0715x over previous
#include <cuda_runtime.h>
#include <cuda_bf16.h>
#include <cstdint>
#include <cstddef>

#define BB 2
#define NNODE 2048
#define DDIM 256
#define HH 8
#define HDIM 32
#define EEDGE 65536
#define KTOP 1024
#define NWRD (NNODE/32)   // 64 u32 words per adjacency row

typedef unsigned u32;
typedef unsigned long long u64;

// ---------------- packed f32x2 helpers ----------------
__device__ __forceinline__ u64 ffma2(u64 a, u64 b, u64 c) {
    u64 d; asm("fma.rn.f32x2 %0, %1, %2, %3;" : "=l"(d) : "l"(a), "l"(b), "l"(c)); return d;
}
__device__ __forceinline__ u64 pk2(float lo, float hi) {
    u64 d; asm("mov.b64 %0, {%1, %2};" : "=l"(d) : "f"(lo), "f"(hi)); return d;
}
__device__ __forceinline__ void upk2(u64 v, float& lo, float& hi) {
    asm("mov.b64 {%0, %1}, %2;" : "=f"(lo), "=f"(hi) : "l"(v));
}
// pack two fp32 -> bf16x2 (hi goes to upper 16 bits)
__device__ __forceinline__ u32 cvt2(float hi, float lo) {
    u32 r; asm("cvt.rn.bf16x2.f32 %0, %1, %2;" : "=r"(r) : "f"(hi), "f"(lo)); return r;
}
__device__ __forceinline__ float bf16rt(float x) {
    return __bfloat162float(__float2bfloat16_rn(x));
}
// mma.sync m16n8k16 bf16 row.col, fp32 accumulate
__device__ __forceinline__ void mma16816(float c[4], const u32 a[4], u32 b0, u32 b1) {
    asm volatile(
        "mma.sync.aligned.m16n8k16.row.col.f32.bf16.bf16.f32 "
        "{%0,%1,%2,%3},{%4,%5,%6,%7},{%8,%9},{%0,%1,%2,%3};"
        : "+f"(c[0]), "+f"(c[1]), "+f"(c[2]), "+f"(c[3])
        : "r"(a[0]), "r"(a[1]), "r"(a[2]), "r"(a[3]), "r"(b0), "r"(b1));
}

// ---------------- scratch (device globals) ----------------
__device__ float g_topo[BB*NNODE];
__device__ u32   g_edge[NNODE*NWRD];
__device__ u32   g_colbits[BB*NWRD];
__device__ u32   g_maskbits[BB*NNODE*NWRD];       // edge | colbits, premerged
// Q: bf16 hi/lo [bh][n][16 words each]
__device__ __nv_bfloat16 g_Qh[(size_t)BB*HH*NNODE*HDIM];
__device__ __nv_bfloat16 g_Ql[(size_t)BB*HH*NNODE*HDIM];
// K interleaved: [bh][n][8 units], unit u = kc*4+tig holds {h[kc*8+tig], h[kc*8+tig+4], l[..], l[..+4]}
__device__ u32 g_Ki[(size_t)BB*HH*NNODE*32];
// V^T interleaved: [bh][d][512 units], unit (jt*32 + s8*4 + p) holds {h[w],h[w+4],l[w],l[w+4]}
__device__ u32 g_Vi[(size_t)BB*HH*HDIM*2048];
__device__ float g_attn[(size_t)BB*NNODE*DDIM];

// ---------------- zero edge bits ----------------
__global__ void k_zero() {
    int i = blockIdx.x * blockDim.x + threadIdx.x;
    if (i < NNODE*NWRD) g_edge[i] = 0u;
}

// ---------------- scatter edges into bitmask ----------------
__global__ void k_scatter(const int* __restrict__ ei) {
    int e = blockIdx.x * blockDim.x + threadIdx.x;
    if (e >= EEDGE) return;
    int r = ei[e];
    int c = ei[EEDGE + e];
    atomicOr(&g_edge[r * NWRD + (c >> 5)], 1u << (c & 31));
}

// ---------------- topo scores (f32x2 packed) ----------------
__global__ void __launch_bounds__(128) k_topo(const float* __restrict__ x,
                       const float* __restrict__ g1w, const float* __restrict__ g1b,
                       const float* __restrict__ g2w, const float* __restrict__ g2b) {
    __shared__ __align__(16) float xs[8][DDIM];
    __shared__ float rs[8][4];
    int t = threadIdx.x;
    int base = blockIdx.x * 8;

    const float4* xv = (const float4*)(x + (size_t)base * DDIM);
    float4* xsv = (float4*)&xs[0][0];
    #pragma unroll
    for (int r = 0; r < 4; r++) xsv[t + r * 128] = xv[t + r * 128];
    __syncthreads();

    u64 acc[8];
    #pragma unroll
    for (int nn = 0; nn < 8; nn++) acc[nn] = 0ull;

    const ulonglong2* wrow = (const ulonglong2*)(g1w + (size_t)t * DDIM);
    #pragma unroll 4
    for (int k4 = 0; k4 < DDIM/4; k4++) {
        ulonglong2 wv = wrow[k4];
        #pragma unroll
        for (int nn = 0; nn < 8; nn++) {
            ulonglong2 xp = ((const ulonglong2*)xs[nn])[k4];
            acc[nn] = ffma2(wv.x, xp.x, acc[nn]);
            acc[nn] = ffma2(wv.y, xp.y, acc[nn]);
        }
    }
    float b1 = g1b[t];
    float w2s = g2w[t];
    float res[8];
    #pragma unroll
    for (int nn = 0; nn < 8; nn++) {
        float lo, hi; upk2(acc[nn], lo, hi);
        float h = fmaxf(lo + hi + b1, 0.0f);
        res[nn] = h * w2s;
    }
    int lane = t & 31, wrp = t >> 5;
    #pragma unroll
    for (int nn = 0; nn < 8; nn++) {
        float v = res[nn];
        #pragma unroll
        for (int o = 16; o > 0; o >>= 1) v += __shfl_down_sync(0xffffffffu, v, o);
        if (lane == 0) rs[nn][wrp] = v;
    }
    __syncthreads();
    if (t < 8) {
        float v = rs[t][0] + rs[t][1] + rs[t][2] + rs[t][3];
        g_topo[base + t] = v + g2b[0];
    }
}

// ---------------- exact top-k: radix select with parallel threshold find ----------------
__global__ void __launch_bounds__(256) k_topk() {
    __shared__ u32 keys[NNODE];
    __shared__ u32 hist[256];
    __shared__ u32 sb[256];
    __shared__ u32 scn[256];
    __shared__ u32 sh_prefix, sh_remain;
    int b = blockIdx.x;
    int t = threadIdx.x;  // 256 threads

    if (t < NWRD) g_colbits[b * NWRD + t] = 0u;   // own row only; used after final barrier

    for (int i = t; i < NNODE; i += 256) {
        u32 u = __float_as_uint(g_topo[b * NNODE + i]);
        u = (u & 0x80000000u) ? ~u : (u | 0x80000000u);  // monotone ascending
        keys[i] = u;
    }
    u32 prefix = 0, remain = KTOP;
    __syncthreads();

    for (int shift = 24; shift >= 0; shift -= 8) {
        hist[t] = 0;
        __syncthreads();
        for (int i = t; i < NNODE; i += 256) {
            u32 k = keys[i];
            bool in_group = (shift == 24) || ((k >> (shift + 8)) == prefix);
            if (in_group) atomicAdd(&hist[(k >> shift) & 255], 1u);
        }
        __syncthreads();
        // parallel inclusive SUFFIX sum: sb[v] = sum_{u>=v} hist[u]
        sb[t] = hist[t];
        __syncthreads();
        for (int ofs = 1; ofs < 256; ofs <<= 1) {
            u32 add = (t + ofs < 256) ? sb[t + ofs] : 0u;
            __syncthreads();
            sb[t] += add;
            __syncthreads();
        }
        u32 above = (t == 255) ? 0u : sb[t + 1];
        if (sb[t] >= remain && above < remain) {
            sh_prefix = (prefix << 8) | (u32)t;
            sh_remain = remain - above;
        }
        __syncthreads();
        prefix = sh_prefix;
        remain = sh_remain;
        __syncthreads();
    }
    u32 T = prefix;  // KTOP-th largest key; take `remain` of the ==T set in index order

    u32 cnt = 0;
    #pragma unroll
    for (int u = 0; u < 8; u++) if (keys[t * 8 + u] == T) cnt++;
    scn[t] = cnt;
    __syncthreads();
    for (int ofs = 1; ofs < 256; ofs <<= 1) {
        u32 v = scn[t];
        u32 add = (t >= ofs) ? scn[t - ofs] : 0u;
        __syncthreads();
        scn[t] = v + add;
        __syncthreads();
    }
    u32 taken = scn[t] - cnt;
    u32 byte = 0;
    #pragma unroll
    for (int u = 0; u < 8; u++) {
        u32 k = keys[t * 8 + u];
        bool m = false;
        if (k > T) m = true;
        else if (k == T) { if (taken < remain) m = true; taken++; }
        if (m) byte |= (1u << u);
    }
    atomicOr(&g_colbits[b * NWRD + (t >> 2)], byte << ((t & 3) * 8));
}

// ---------------- premerge mask bits: maskbits[b][i][w] = edge[i][w] | colbits[b][w] ----------------
__global__ void k_merge() {
    int idx = blockIdx.x * 256 + threadIdx.x;   // 65536 uint4
    int b = idx >> 15, rem = idx & 32767;
    int i = rem >> 4, w = rem & 15;
    uint4 e = ((const uint4*)g_edge)[i * 16 + w];
    uint4 c = ((const uint4*)g_colbits)[b * 16 + w];
    ((uint4*)g_maskbits)[idx] = make_uint4(e.x | c.x, e.y | c.y, e.z | c.z, e.w | c.w);
}

// ---------------- fused QKV GEMM (f32x2 core), blockIdx.z selects Q/K/V ----------------
__global__ void __launch_bounds__(256) k_gemmQKV(
        const float* __restrict__ A,
        const float* __restrict__ qw, const float* __restrict__ qb,
        const float* __restrict__ kw, const float* __restrict__ kb,
        const float* __restrict__ vw, const float* __restrict__ vb,
        u32* __restrict__ Qh, u32* __restrict__ Ql,
        u32* __restrict__ Ki, u32* __restrict__ Vi, float qscale) {
    __shared__ __align__(16) u64   As2[16][130];
    __shared__ __align__(16) float Ws[16][68];
    int mode = blockIdx.z;
    const float* W    = (mode == 0) ? qw : (mode == 1) ? kw : vw;
    const float* bias = (mode == 0) ? qb : (mode == 1) ? kb : vb;
    float scale = (mode == 0) ? qscale : 1.0f;

    int tid = threadIdx.x;
    int tx = tid & 15;       // col group: cols c0 + tx*4 + {0..3}
    int rg = tid >> 4;       // row group: rows m0 + rg*8 + {0..7}
    int m0 = blockIdx.x * 128, c0 = blockIdx.y * 64;
    int lkk = tid & 15, lm = tid >> 4;

    u64 acc[8][2];
    #pragma unroll
    for (int i = 0; i < 8; i++) { acc[i][0] = 0ull; acc[i][1] = 0ull; }

    for (int k0 = 0; k0 < DDIM; k0 += 16) {
        #pragma unroll
        for (int rr = 0; rr < 8; rr++) {
            int m = lm + 16 * rr;
            float v = A[(size_t)(m0 + m) * DDIM + k0 + lkk];
            As2[lkk][m] = pk2(v, v);
        }
        #pragma unroll
        for (int rr = 0; rr < 4; rr++) {
            int c = lm + 16 * rr;
            Ws[lkk][c] = W[(size_t)(c0 + c) * DDIM + k0 + lkk];
        }
        __syncthreads();
        #pragma unroll
        for (int kk = 0; kk < 16; kk++) {
            float4 w4 = *(const float4*)&Ws[kk][tx * 4];
            u64 w01 = pk2(w4.x, w4.y), w23 = pk2(w4.z, w4.w);
            const u64* arow = &As2[kk][rg * 8];
            #pragma unroll
            for (int ii = 0; ii < 8; ii += 2) {
                ulonglong2 a2 = *(const ulonglong2*)&arow[ii];
                acc[ii][0]     = ffma2(a2.x, w01, acc[ii][0]);
                acc[ii][1]     = ffma2(a2.x, w23, acc[ii][1]);
                acc[ii + 1][0] = ffma2(a2.y, w01, acc[ii + 1][0]);
                acc[ii + 1][1] = ffma2(a2.y, w23, acc[ii + 1][1]);
            }
        }
        __syncthreads();
    }

    float4 b4 = *(const float4*)&bias[c0 + tx * 4];
    int c = c0 + tx * 4;                 // 4 consecutive cols (same head)
    int h = (c >> 5) & 7, cw = c & 31;
    int bb = m0 >> 11;                   // m0 multiple of 128, no batch straddle
    int n0 = (m0 & 2047) + rg * 8;
    int bh = bb * HH + h;

    if (mode == 2) {
        // V: transposed, interleaved hi/lo units in gmem
        float vals[8][4];
        #pragma unroll
        for (int ii = 0; ii < 8; ii++) {
            float f0, f1, f2, f3;
            upk2(acc[ii][0], f0, f1);
            upk2(acc[ii][1], f2, f3);
            vals[ii][0] = f0 + b4.x; vals[ii][1] = f1 + b4.y;
            vals[ii][2] = f2 + b4.z; vals[ii][3] = f3 + b4.w;
        }
        int w0v = n0 >> 1;                       // 4-aligned global word
        int jt = w0v >> 6;
        int s8 = (w0v & 63) >> 3;
        int slot = (w0v >> 2) & 1;               // (w0v&7)>>2
        #pragma unroll
        for (int jj = 0; jj < 4; jj++) {
            int d = cw + jj;
            size_t dbase = ((size_t)bh * HDIM + d) * 2048;
            #pragma unroll
            for (int p = 0; p < 4; p++) {
                float v0 = vals[2*p][jj], v1 = vals[2*p+1][jj];
                float h0 = bf16rt(v0), h1 = bf16rt(v1);
                size_t ub = dbase + (size_t)(jt * 32 + s8 * 4 + p) * 4;
                Vi[ub + slot]     = cvt2(h1, h0);
                Vi[ub + slot + 2] = cvt2(v1 - h1, v0 - h0);
            }
        }
    } else if (mode == 1) {
        // K: interleaved hi/lo units in gmem
        int w0 = cw >> 1;                        // even
        int kc = w0 >> 3, t0 = w0 & 7;
        int u0 = kc * 4 + (t0 & 3);
        int s = t0 >> 2;
        #pragma unroll
        for (int ii = 0; ii < 8; ii++) {
            float f0, f1, f2, f3;
            upk2(acc[ii][0], f0, f1);
            upk2(acc[ii][1], f2, f3);
            f0 += b4.x; f1 += b4.y; f2 += b4.z; f3 += b4.w;
            float h0 = bf16rt(f0), h1 = bf16rt(f1), h2 = bf16rt(f2), h3 = bf16rt(f3);
            int n = n0 + ii;
            size_t rb = ((size_t)bh * NNODE + n) * 32;
            Ki[rb + u0*4 + s]           = cvt2(h1, h0);
            Ki[rb + (u0+1)*4 + s]       = cvt2(h3, h2);
            Ki[rb + u0*4 + s + 2]       = cvt2(f1 - h1, f0 - h0);
            Ki[rb + (u0+1)*4 + s + 2]   = cvt2(f3 - h3, f2 - h2);
        }
    } else {
        // Q: hi/lo arrays [bh][n][16 words], scaled
        #pragma unroll
        for (int ii = 0; ii < 8; ii++) {
            float f0, f1, f2, f3;
            upk2(acc[ii][0], f0, f1);
            upk2(acc[ii][1], f2, f3);
            f0 = (f0 + b4.x) * scale; f1 = (f1 + b4.y) * scale;
            f2 = (f2 + b4.z) * scale; f3 = (f3 + b4.w) * scale;
            float h0 = bf16rt(f0), h1 = bf16rt(f1), h2 = bf16rt(f2), h3 = bf16rt(f3);
            int n = n0 + ii;
            size_t widx = ((size_t)bh * NNODE + n) * (HDIM/2) + (cw >> 1);
            *(uint2*)&Qh[widx] = make_uint2(cvt2(h1, h0), cvt2(h3, h2));
            *(uint2*)&Ql[widx] = make_uint2(cvt2(f1 - h1, f0 - h0), cvt2(f3 - h3, f2 - h2));
        }
    }
}

// ---------------- O projection GEMM (fp32 out) ----------------
__global__ void __launch_bounds__(256) k_gemmO(const float* __restrict__ A, const float* __restrict__ W,
                       const float* __restrict__ bias, float* __restrict__ OutF) {
    __shared__ __align__(16) u64   As2[16][130];
    __shared__ __align__(16) float Ws[16][68];
    int tid = threadIdx.x;
    int tx = tid & 15;
    int rg = tid >> 4;
    int m0 = blockIdx.x * 128, c0 = blockIdx.y * 64;
    int lkk = tid & 15, lm = tid >> 4;

    u64 acc[8][2];
    #pragma unroll
    for (int i = 0; i < 8; i++) { acc[i][0] = 0ull; acc[i][1] = 0ull; }

    for (int k0 = 0; k0 < DDIM; k0 += 16) {
        #pragma unroll
        for (int rr = 0; rr < 8; rr++) {
            int m = lm + 16 * rr;
            float v = A[(size_t)(m0 + m) * DDIM + k0 + lkk];
            As2[lkk][m] = pk2(v, v);
        }
        #pragma unroll
        for (int rr = 0; rr < 4; rr++) {
            int c = lm + 16 * rr;
            Ws[lkk][c] = W[(size_t)(c0 + c) * DDIM + k0 + lkk];
        }
        __syncthreads();
        #pragma unroll
        for (int kk = 0; kk < 16; kk++) {
            float4 w4 = *(const float4*)&Ws[kk][tx * 4];
            u64 w01 = pk2(w4.x, w4.y), w23 = pk2(w4.z, w4.w);
            const u64* arow = &As2[kk][rg * 8];
            #pragma unroll
            for (int ii = 0; ii < 8; ii += 2) {
                ulonglong2 a2 = *(const ulonglong2*)&arow[ii];
                acc[ii][0]     = ffma2(a2.x, w01, acc[ii][0]);
                acc[ii][1]     = ffma2(a2.x, w23, acc[ii][1]);
                acc[ii + 1][0] = ffma2(a2.y, w01, acc[ii + 1][0]);
                acc[ii + 1][1] = ffma2(a2.y, w23, acc[ii + 1][1]);
            }
        }
        __syncthreads();
    }

    float4 b4 = *(const float4*)&bias[c0 + tx * 4];
    int c = c0 + tx * 4;
    #pragma unroll
    for (int ii = 0; ii < 8; ii++) {
        int m = m0 + rg * 8 + ii;
        float f0, f1, f2, f3;
        upk2(acc[ii][0], f0, f1);
        upk2(acc[ii][1], f2, f3);
        *(float4*)&OutF[(size_t)m * DDIM + c] =
            make_float4(f0 + b4.x, f1 + b4.y, f2 + b4.z, f3 + b4.w);
    }
}

// ---------------- fused masked attention + mask writeback ----------------
// block: 128 thr (4 warps), one (bh), 128 query rows. warp wp owns rows
// {wp*16..+15} (set0) and {64+wp*16..+15} (set1). B-fragments loaded once
// via LDS.128 (interleaved layout), reused by both A-sets (6 MMAs per load).
__global__ void __launch_bounds__(128) k_attn(float* __restrict__ outMask) {
    __shared__ __align__(16) uint4 Ks4[128 * 12];   // stride 12 units (192B): conflict-free .128
    __shared__ __align__(16) uint4 Vs4[32 * 36];    // stride 36 units (576B)
    __shared__ __align__(16) u32 eW[128][4];

    int tid = threadIdx.x;
    int wp = tid >> 5, lane = tid & 31;
    int gid = lane >> 2, tig = lane & 3;
    int bh = blockIdx.y, b = bh >> 3, h = bh & 7;
    int i0 = blockIdx.x * 128;

    const u32* gqh = (const u32*)g_Qh;
    const u32* gql = (const u32*)g_Ql;
    const uint4* gKi = (const uint4*)g_Ki;
    const uint4* gVi = (const uint4*)g_Vi;
    const uint4* gM  = (const uint4*)g_maskbits;

    // Q A-fragments for both sets (scale already folded)
    u32 qh[2][2][4], ql[2][2][4];
    #pragma unroll
    for (int s = 0; s < 2; s++) {
        size_t blo = ((size_t)bh * NNODE + i0 + s * 64 + wp * 16 + gid) * 16;
        size_t bhi = blo + 8 * 16;
        #pragma unroll
        for (int kc = 0; kc < 2; kc++) {
            qh[s][kc][0] = gqh[blo + kc*8 + tig];
            qh[s][kc][1] = gqh[bhi + kc*8 + tig];
            qh[s][kc][2] = gqh[blo + kc*8 + tig + 4];
            qh[s][kc][3] = gqh[bhi + kc*8 + tig + 4];
            ql[s][kc][0] = gql[blo + kc*8 + tig];
            ql[s][kc][1] = gql[bhi + kc*8 + tig];
            ql[s][kc][2] = gql[blo + kc*8 + tig + 4];
            ql[s][kc][3] = gql[bhi + kc*8 + tig + 4];
        }
    }

    float oc[2][4][4];
    #pragma unroll
    for (int s = 0; s < 2; s++)
        #pragma unroll
        for (int vt = 0; vt < 4; vt++)
            #pragma unroll
            for (int e = 0; e < 4; e++) oc[s][vt][e] = 0.0f;
    float sl[2] = {0.0f, 0.0f}, sh[2] = {0.0f, 0.0f};

    for (int j0 = 0; j0 < NNODE; j0 += 128) {
        __syncthreads();
        // stage K (interleaved, 1024 units)
        for (int idx = tid; idx < 1024; idx += 128) {
            int r = idx >> 3, g = idx & 7;
            Ks4[r * 12 + g] = gKi[((size_t)bh * NNODE + j0 + r) * 8 + g];
        }
        // stage V^T (interleaved, 1024 units)
        for (int idx = tid; idx < 1024; idx += 128) {
            int d = idx >> 5, gv = idx & 31;
            Vs4[d * 36 + gv] = gVi[((size_t)bh * HDIM + d) * 512 + (j0 >> 7) * 32 + gv];
        }
        // stage premerged mask bits (1 uint4 per row)
        {
            uint4 m4 = gM[((size_t)(b * NNODE + i0 + tid)) * 16 + (j0 >> 7)];
            *(uint4*)&eW[tid][0] = m4;
        }
        __syncthreads();

        // coalesced sparse_mask writeback (32 rows per warp, streaming)
        {
            #pragma unroll 8
            for (int rr = 0; rr < 32; rr++) {
                int r = wp + rr * 4;
                u32 bits = eW[r][lane >> 3];
                int bo = (lane & 7) * 4;
                float4 f;
                f.x = (bits >> (bo + 0)) & 1u ? 1.0f : 0.0f;
                f.y = (bits >> (bo + 1)) & 1u ? 1.0f : 0.0f;
                f.z = (bits >> (bo + 2)) & 1u ? 1.0f : 0.0f;
                f.w = (bits >> (bo + 3)) & 1u ? 1.0f : 0.0f;
                __stcs((float4*)(outMask + ((size_t)bh * NNODE + i0 + r) * NNODE + j0) + lane, f);
            }
        }

        #pragma unroll 1
        for (int sub = 0; sub < 4; sub++) {
            // ---- S = Q K^T for both sets (shared B-fragments) ----
            float sc[2][4][4];
            #pragma unroll
            for (int s = 0; s < 2; s++)
                #pragma unroll
                for (int nt = 0; nt < 4; nt++)
                    #pragma unroll
                    for (int e = 0; e < 4; e++) sc[s][nt][e] = 0.0f;
            #pragma unroll
            for (int kc = 0; kc < 2; kc++)
                #pragma unroll
                for (int nt = 0; nt < 4; nt++) {
                    int jr = sub * 32 + nt * 8 + gid;
                    uint4 kf = Ks4[jr * 12 + kc * 4 + tig];
                    mma16816(sc[0][nt], qh[0][kc], kf.x, kf.y);
                    mma16816(sc[0][nt], ql[0][kc], kf.x, kf.y);
                    mma16816(sc[0][nt], qh[0][kc], kf.z, kf.w);
                    mma16816(sc[1][nt], qh[1][kc], kf.x, kf.y);
                    mma16816(sc[1][nt], ql[1][kc], kf.x, kf.y);
                    mma16816(sc[1][nt], qh[1][kc], kf.z, kf.w);
                }
            // ---- exp + mask + pack per set ----
            u32 ph[2][2][4], pl[2][2][4];
            #pragma unroll
            for (int s = 0; s < 2; s++) {
                u32 wlo = eW[s * 64 + wp * 16 + gid][sub];
                u32 whi = eW[s * 64 + wp * 16 + gid + 8][sub];
                float pm[4][4];
                #pragma unroll
                for (int nt = 0; nt < 4; nt++) {
                    float p0 = __expf(sc[s][nt][0]);
                    float p1 = __expf(sc[s][nt][1]);
                    float p2 = __expf(sc[s][nt][2]);
                    float p3 = __expf(sc[s][nt][3]);
                    int bp = nt * 8 + tig * 2;
                    float m0 = ((wlo >> bp) & 1u) ? p0 : 0.0f;
                    float m1 = ((wlo >> (bp + 1)) & 1u) ? p1 : 0.0f;
                    float m2 = ((whi >> bp) & 1u) ? p2 : 0.0f;
                    float m3 = ((whi >> (bp + 1)) & 1u) ? p3 : 0.0f;
                    sl[s] += m0 + m1; sh[s] += m2 + m3;
                    pm[nt][0] = m0; pm[nt][1] = m1; pm[nt][2] = m2; pm[nt][3] = m3;
                }
                #pragma unroll
                for (int kc = 0; kc < 2; kc++) {
                    int na = kc * 2, nb = kc * 2 + 1;
                    float h00 = bf16rt(pm[na][0]), h01 = bf16rt(pm[na][1]);
                    float h02 = bf16rt(pm[na][2]), h03 = bf16rt(pm[na][3]);
                    float h10 = bf16rt(pm[nb][0]), h11 = bf16rt(pm[nb][1]);
                    float h12 = bf16rt(pm[nb][2]), h13 = bf16rt(pm[nb][3]);
                    ph[s][kc][0] = cvt2(h01, h00);
                    ph[s][kc][1] = cvt2(h03, h02);
                    ph[s][kc][2] = cvt2(h11, h10);
                    ph[s][kc][3] = cvt2(h13, h12);
                    pl[s][kc][0] = cvt2(pm[na][1] - h01, pm[na][0] - h00);
                    pl[s][kc][1] = cvt2(pm[na][3] - h03, pm[na][2] - h02);
                    pl[s][kc][2] = cvt2(pm[nb][1] - h11, pm[nb][0] - h10);
                    pl[s][kc][3] = cvt2(pm[nb][3] - h13, pm[nb][2] - h12);
                }
            }
            // ---- O += P V for both sets (shared B-fragments) ----
            #pragma unroll
            for (int kc = 0; kc < 2; kc++)
                #pragma unroll
                for (int vt = 0; vt < 4; vt++) {
                    int d = vt * 8 + gid;
                    uint4 vf = Vs4[d * 36 + (sub * 2 + kc) * 4 + tig];
                    mma16816(oc[0][vt], ph[0][kc], vf.x, vf.y);
                    mma16816(oc[0][vt], pl[0][kc], vf.x, vf.y);
                    mma16816(oc[0][vt], ph[0][kc], vf.z, vf.w);
                    mma16816(oc[1][vt], ph[1][kc], vf.x, vf.y);
                    mma16816(oc[1][vt], pl[1][kc], vf.x, vf.y);
                    mma16816(oc[1][vt], ph[1][kc], vf.z, vf.w);
                }
        }
    }

    // reduce S across quads; normalize; store both sets
    #pragma unroll
    for (int s = 0; s < 2; s++) {
        float slo = sl[s], shi = sh[s];
        #pragma unroll
        for (int o = 1; o <= 2; o <<= 1) {
            slo += __shfl_xor_sync(0xffffffffu, slo, o);
            shi += __shfl_xor_sync(0xffffffffu, shi, o);
        }
        float invlo = 1.0f / slo;
        float invhi = 1.0f / shi;
        int nlo = i0 + s * 64 + wp * 16 + gid;
        int nhi = nlo + 8;
        size_t olo = ((size_t)(b * NNODE + nlo)) * DDIM + h * HDIM;
        size_t ohi = ((size_t)(b * NNODE + nhi)) * DDIM + h * HDIM;
        #pragma unroll
        for (int vt = 0; vt < 4; vt++) {
            int d = vt * 8 + tig * 2;
            *(float2*)&g_attn[olo + d] = make_float2(oc[s][vt][0] * invlo, oc[s][vt][1] * invlo);
            *(float2*)&g_attn[ohi + d] = make_float2(oc[s][vt][2] * invhi, oc[s][vt][3] * invhi);
        }
    }
}

// ---------------- launch (single stream; graph-capturable) ----------------
extern "C" void kernel_launch(void* const* d_in, const int* in_sizes, int n_in,
                              void* d_out, int out_size) {
    (void)in_sizes; (void)n_in; (void)out_size;
    const float* x   = (const float*)d_in[0];
    const int*   ei  = (const int*)  d_in[1];
    const float* qw  = (const float*)d_in[2];
    const float* qb  = (const float*)d_in[3];
    const float* kw  = (const float*)d_in[4];
    const float* kb  = (const float*)d_in[5];
    const float* vw  = (const float*)d_in[6];
    const float* vb  = (const float*)d_in[7];
    const float* ow  = (const float*)d_in[8];
    const float* ob  = (const float*)d_in[9];
    const float* g1w = (const float*)d_in[10];
    const float* g1b = (const float*)d_in[11];
    const float* g2w = (const float*)d_in[12];
    const float* g2b = (const float*)d_in[13];

    float* out = (float*)d_out;
    float* outMask = out + (size_t)BB * NNODE * DDIM;

    u32 *pQh, *pQl, *pKi, *pVi;
    float* pAttn;
    cudaGetSymbolAddress((void**)&pQh, g_Qh);
    cudaGetSymbolAddress((void**)&pQl, g_Ql);
    cudaGetSymbolAddress((void**)&pKi, g_Ki);
    cudaGetSymbolAddress((void**)&pVi, g_Vi);
    cudaGetSymbolAddress((void**)&pAttn, g_attn);

    const float qscale = 0.17677669529663687f;  // 1/sqrt(32)

    k_zero<<<512, 256>>>();
    k_scatter<<<EEDGE / 256, 256>>>(ei);
    k_topo<<<BB * NNODE / 8, 128>>>(x, g1w, g1b, g2w, g2b);
    k_topk<<<BB, 256>>>();
    k_merge<<<256, 256>>>();

    dim3 qkvgrid(BB * NNODE / 128, DDIM / 64, 3);
    k_gemmQKV<<<qkvgrid, 256>>>(x, qw, qb, kw, kb, vw, vb,
                                pQh, pQl, pKi, pVi, qscale);

    k_attn<<<dim3(NNODE / 128, BB * HH), 128>>>(outMask);

    dim3 ogrid(BB * NNODE / 128, DDIM / 64);
    k_gemmO<<<ogrid, 256>>>(pAttn, ow, ob, out);
}